// round 11
// baseline (speedup 1.0000x reference)
#include <cuda_runtime.h>
#include <cuda_bf16.h>
#include <cuda_fp8.h>
#include <math.h>
#include <cstdint>

// ---------------------------------------------------------------------------
// Problem constants
// ---------------------------------------------------------------------------
namespace {
constexpr int B_FULL  = 2048;
constexpr int N_PIX   = 1024;
constexpr int T_DIV   = 64;
constexpr int C_CLS   = 10;
constexpr int PER_DIV = 16;
constexpr int K_DIM   = 512;          // k = i*4 + m (w_mid memory order)
constexpr int R_RANK  = 128;
constexpr int BT      = 64;           // batch rows per CTA
constexpr int NTHR    = 256;          // 8 warps: 2(m) x 4(n), warp tile m32 x n32
constexpr int NKT     = 16;           // k32 tiles

constexpr int PADK8   = 528;          // fp8 row stride (bytes); 528 mod 128 = 16 -> conflict-free

// smem byte offsets
constexpr int OFF_B   = 0;                          // [128][528] fp8 = 67584
constexpr int OFF_A   = OFF_B + R_RANK * PADK8;     // [64][528] fp8 = 33792
constexpr int OFF_X   = OFF_A + BT * PADK8;         // 64 float4 = 1024
constexpr int OFF_S0  = OFF_X + 1024;               // 128 f32
constexpr int OFF_WL  = OFF_S0 + 512;               // 128 f32
constexpr int OFF_RED = OFF_WL + 512;               // 64*16 f32 = 4096
constexpr int OFF_MAX = OFF_RED + 4096;             // 8 f32
constexpr int SMEM_BYTES = OFF_MAX + 64;            // ~107 KB
}

// ---------------------------------------------------------------------------
// Device scratch
// ---------------------------------------------------------------------------
__device__ float4 g_div4[T_DIV * B_FULL];      // [t][b] -> M=4 features
__device__ float  g_logits[B_FULL * C_CLS];    // [b][c]

// ---------------------------------------------------------------------------
// asm helpers
// ---------------------------------------------------------------------------
__device__ __forceinline__ uint32_t smem_to_u32(const void* p) {
    uint32_t a;
    asm("{ .reg .u64 t; cvta.to.shared.u64 t, %1; cvt.u32.u64 %0, t; }" : "=r"(a) : "l"(p));
    return a;
}
__device__ __forceinline__ void ldsm4(uint32_t* r, uint32_t addr) {
    asm volatile("ldmatrix.sync.aligned.m8n8.x4.shared.b16 {%0,%1,%2,%3}, [%4];"
                 : "=r"(r[0]), "=r"(r[1]), "=r"(r[2]), "=r"(r[3]) : "r"(addr));
}
// fp8 e4m3 mma: m16n8k32, fp32 accumulate (sm_89+)
__device__ __forceinline__ void mma16832f8(float* d, const uint32_t* a, uint32_t b0, uint32_t b1) {
    asm volatile("mma.sync.aligned.m16n8k32.row.col.f32.e4m3.e4m3.f32 "
                 "{%0,%1,%2,%3}, {%4,%5,%6,%7}, {%8,%9}, {%0,%1,%2,%3};"
                 : "+f"(d[0]), "+f"(d[1]), "+f"(d[2]), "+f"(d[3])
                 : "r"(a[0]), "r"(a[1]), "r"(a[2]), "r"(a[3]), "r"(b0), "r"(b1));
}
// pack 4 floats into 4 e4m3 bytes (v0 = lowest byte)
__device__ __forceinline__ uint32_t pack4e4m3(float v0, float v1, float v2, float v3) {
    uint16_t h0, h1; uint32_t u;
    asm("cvt.rn.satfinite.e4m3x2.f32 %0, %1, %2;" : "=h"(h0) : "f"(v1), "f"(v0));
    asm("cvt.rn.satfinite.e4m3x2.f32 %0, %1, %2;" : "=h"(h1) : "f"(v3), "f"(v2));
    asm("mov.b32 %0, {%1, %2};" : "=r"(u) : "h"(h0), "h"(h1));
    return u;
}
__device__ __forceinline__ uint8_t f2e4m3(float v) {
    uint16_t h;
    asm("cvt.rn.satfinite.e4m3x2.f32 %0, %1, %2;" : "=h"(h) : "f"(0.f), "f"(v));
    return (uint8_t)(h & 0xFF);
}

// ---------------------------------------------------------------------------
// Kernel 1: feature map + division averaging
// ---------------------------------------------------------------------------
__global__ void feat_kernel(const float* __restrict__ tensor) {
    int idx = blockIdx.x * blockDim.x + threadIdx.x;
    if (idx >= B_FULL * T_DIV) return;
    int b = idx >> 6;
    int t = idx & (T_DIV - 1);
    const float4* p = reinterpret_cast<const float4*>(tensor + b * N_PIX + t * PER_DIV);
    float a0 = 0.f, a1 = 0.f, a2 = 0.f, a3 = 0.f;
#pragma unroll
    for (int j = 0; j < 4; ++j) {
        float4 v = p[j];
        float xs[4] = {v.x, v.y, v.z, v.w};
#pragma unroll
        for (int q = 0; q < 4; ++q) {
            float ang = 1.57079632679489662f * xs[q];
            float s, c;
            sincosf(ang, &s, &c);
            float c2 = c * c, s2 = s * s;
            a0 += c2 * c; a1 += c2 * s; a2 += c * s2; a3 += s2 * s;
        }
    }
    const float inv = 1.0f / (float)PER_DIV;
    g_div4[t * B_FULL + b] = make_float4(a0 * inv, a1 * inv, a2 * inv, a3 * inv);
}

// ---------------------------------------------------------------------------
// Kernel 2: TT recurrence via fp8 e4m3 mma (fp32 accum), R8 flat skeleton.
// ALL of B (16 k32-tiles) persists in registers; A-only LDSM per step.
// Exact scaling: B staged as W*2^8; A scaled 2^-e_t per step from tracked
// max|state|; F = sum(8 - e_t); final logits *= 2^-F.
// ---------------------------------------------------------------------------
__global__ __launch_bounds__(NTHR) void rec_fp8_kernel(const float* __restrict__ w_first,
                                                       const float* __restrict__ w_mid,
                                                       const float* __restrict__ w_last) {
    extern __shared__ char smem[];
    const int tid = threadIdx.x;
    const int l   = tid & 31;
    const int wid = tid >> 5;
    const int mg  = wid & 1;      // m-group: rows mg*32 .. +31
    const int ng  = wid >> 1;     // n-group: cols ng*32 .. +31
    const int c   = blockIdx.y;
    const int b0  = blockIdx.x * BT;

    const uint32_t smem_u = smem_to_u32(smem);
    float*  s0s  = reinterpret_cast<float*>(smem + OFF_S0);
    float*  wls  = reinterpret_cast<float*>(smem + OFF_WL);
    float4* sX   = reinterpret_cast<float4*>(smem + OFF_X);
    float*  sRed = reinterpret_cast<float*>(smem + OFF_RED);
    float*  sMax = reinterpret_cast<float*>(smem + OFF_MAX);

    // ---- stage B: fp8(W[k][o] * 256), row o, byte col k, stride 528 ----
    {
        const float* Wc = w_mid + c * (K_DIM * R_RANK);
        for (int q = tid; q < K_DIM * R_RANK / 4; q += NTHR) {
            int k = q >> 5;
            int j = (q & 31) << 2;
            float4 v = *reinterpret_cast<const float4*>(Wc + k * R_RANK + j);
            smem[OFF_B + (j + 0) * PADK8 + k] = (char)f2e4m3(v.x * 256.f);
            smem[OFF_B + (j + 1) * PADK8 + k] = (char)f2e4m3(v.y * 256.f);
            smem[OFF_B + (j + 2) * PADK8 + k] = (char)f2e4m3(v.z * 256.f);
            smem[OFF_B + (j + 3) * PADK8 + k] = (char)f2e4m3(v.w * 256.f);
        }
    }
    if (tid < R_RANK) {
        const float* wf = w_first + c * 512;
        s0s[tid] = wf[tid] + wf[128 + tid] + wf[256 + tid] + wf[384 + tid];
        const float* wl = w_last + c * 512;
        wls[tid] = wl[4 * tid] + wl[4 * tid + 1] + wl[4 * tid + 2] + wl[4 * tid + 3];
    }
    __syncthreads();

    // ldmatrix bases: 16-row x 16-b16 (=32 fp8) tiles, canonical x4 mapping
    uint32_t aBase[2], bBase[2];
#pragma unroll
    for (int mt = 0; mt < 2; ++mt)
        aBase[mt] = smem_u + OFF_A +
            (mg * 32 + mt * 16 + (l & 7) + ((l >> 3) & 1) * 8) * PADK8 + (l >> 4) * 16;
#pragma unroll
    for (int p = 0; p < 2; ++p)
        bBase[p] = smem_u + OFF_B +
            (ng * 32 + p * 16 + (l >> 4) * 8 + (l & 7)) * PADK8 + ((l >> 3) & 1) * 16;

    // ---- entire B in registers: 16 kt x 2 p x 4 regs = 128 regs ----
    uint32_t Bp[NKT][2][4];
#pragma unroll
    for (int kt = 0; kt < NKT; ++kt) {
        ldsm4(Bp[kt][0], bBase[0] + kt * 32);
        ldsm4(Bp[kt][1], bBase[1] + kt * 32);
    }

    float acc[2][4][4];
    const int g  = l >> 2;
    const int cc = l & 3;
    int F = 0;                       // exact exponent ledger

    float4 gx = make_float4(0.f, 0.f, 0.f, 0.f);
    if (tid < BT) gx = g_div4[b0 + tid];

    for (int t = 0; t < T_DIV; ++t) {
        if (tid < BT) sX[tid] = gx;
        __syncthreads();   // sX/sMax ready; previous GEMM done with sA

        float ascale;
        int e;
        if (t == 0) {
            e = -5; ascale = 32.f;   // |s0| <~ 1.5 -> A max <~ 48
        } else {
            float mm = 1e-20f;
#pragma unroll
            for (int w = 0; w < 8; ++w) mm = fmaxf(mm, sMax[w]);
            e = (int)floorf(log2f(mm)) - 6;          // target A max ~ 64
            ascale = exp2f((float)(-e));
        }
        F += 8 - e;

        if (t == 0) {
            // A[b][4i+m] = e4m3(s0[i]*x[b][m]*32); thread owns i = tid&127
            int i  = tid & 127;
            int bh = tid >> 7;
            float s = s0s[i] * 32.f;
            for (int b = bh * 32; b < bh * 32 + 32; ++b) {
                float4 x = sX[b];
                *reinterpret_cast<uint32_t*>(smem + OFF_A + b * PADK8 + 4 * i) =
                    pack4e4m3(s * x.x, s * x.y, s * x.z, s * x.w);
            }
        } else {
            // convert this warp's D fragments into A (fp8, scaled)
#pragma unroll
            for (int mt = 0; mt < 2; ++mt) {
                int r = mg * 32 + mt * 16 + g;
                float4 xa = sX[r];
                float4 xb = sX[r + 8];
                float xa0 = xa.x * ascale, xa1 = xa.y * ascale, xa2 = xa.z * ascale, xa3 = xa.w * ascale;
                float xb0 = xb.x * ascale, xb1 = xb.y * ascale, xb2 = xb.z * ascale, xb3 = xb.w * ascale;
#pragma unroll
                for (int nt = 0; nt < 4; ++nt) {
                    int i0 = ng * 32 + nt * 8 + 2 * cc;
                    float c0 = acc[mt][nt][0], c1 = acc[mt][nt][1];
                    float c2 = acc[mt][nt][2], c3 = acc[mt][nt][3];
                    uint2 ua, ub;
                    ua.x = pack4e4m3(c0 * xa0, c0 * xa1, c0 * xa2, c0 * xa3);
                    ua.y = pack4e4m3(c1 * xa0, c1 * xa1, c1 * xa2, c1 * xa3);
                    *reinterpret_cast<uint2*>(smem + OFF_A + r * PADK8 + 4 * i0) = ua;
                    ub.x = pack4e4m3(c2 * xb0, c2 * xb1, c2 * xb2, c2 * xb3);
                    ub.y = pack4e4m3(c3 * xb0, c3 * xb1, c3 * xb2, c3 * xb3);
                    *reinterpret_cast<uint2*>(smem + OFF_A + (r + 8) * PADK8 + 4 * i0) = ub;
                }
            }
        }
#pragma unroll
        for (int mt = 0; mt < 2; ++mt)
#pragma unroll
            for (int nt = 0; nt < 4; ++nt)
#pragma unroll
                for (int q = 0; q < 4; ++q) acc[mt][nt][q] = 0.f;
        __syncthreads();   // sA fully built

        if (tid < BT && t + 1 < T_DIV) gx = g_div4[(t + 1) * B_FULL + b0 + tid];

        // ---- GEMM: 16 k32-tiles, B from registers, A double-buffered ----
        uint32_t Af[2][2][4];
        ldsm4(Af[0][0], aBase[0]);
        ldsm4(Af[0][1], aBase[1]);
#pragma unroll
        for (int kt = 0; kt < NKT; ++kt) {
            int cur = kt & 1, nx = cur ^ 1;
            if (kt < NKT - 1) {
                ldsm4(Af[nx][0], aBase[0] + (kt + 1) * 32);
                ldsm4(Af[nx][1], aBase[1] + (kt + 1) * 32);
            }
#pragma unroll
            for (int nt = 0; nt < 4; ++nt) {
                uint32_t b0v = Bp[kt][nt >> 1][(nt & 1) * 2];
                uint32_t b1v = Bp[kt][nt >> 1][(nt & 1) * 2 + 1];
                mma16832f8(acc[0][nt], Af[cur][0], b0v, b1v);
                mma16832f8(acc[1][nt], Af[cur][1], b0v, b1v);
            }
        }

        // per-warp max|state| for next step's exponent
        float m = 1e-20f;
#pragma unroll
        for (int mt = 0; mt < 2; ++mt)
#pragma unroll
            for (int nt = 0; nt < 4; ++nt)
#pragma unroll
                for (int q = 0; q < 4; ++q) m = fmaxf(m, fabsf(acc[mt][nt][q]));
#pragma unroll
        for (int off = 16; off; off >>= 1) m = fmaxf(m, __shfl_xor_sync(0xFFFFFFFFu, m, off));
        if (l == 0) sMax[wid] = m;
    }

    // ---- final projection: logits[b] = dot(state_b, wl) * 2^-F ----
#pragma unroll
    for (int mt = 0; mt < 2; ++mt) {
        int r = mg * 32 + mt * 16 + g;
        float p0 = 0.f, p1 = 0.f;
#pragma unroll
        for (int nt = 0; nt < 4; ++nt) {
            int i0 = ng * 32 + nt * 8 + 2 * cc;
            float w0 = wls[i0], w1 = wls[i0 + 1];
            p0 += acc[mt][nt][0] * w0 + acc[mt][nt][1] * w1;
            p1 += acc[mt][nt][2] * w0 + acc[mt][nt][3] * w1;
        }
        sRed[r * 16 + ng * 4 + cc]       = p0;
        sRed[(r + 8) * 16 + ng * 4 + cc] = p1;
    }
    __syncthreads();
    if (tid < BT) {
        float sum = 0.f;
#pragma unroll
        for (int q = 0; q < 16; ++q) sum += sRed[tid * 16 + q];
        g_logits[(b0 + tid) * C_CLS + c] = sum * exp2f((float)(-F));
    }
}

// ---------------------------------------------------------------------------
// Kernel 3: log_softmax over C=10
// ---------------------------------------------------------------------------
__global__ void lsm_kernel(float* __restrict__ out) {
    int b = blockIdx.x * blockDim.x + threadIdx.x;
    if (b >= B_FULL) return;
    float v[C_CLS];
    float mx = -INFINITY;
#pragma unroll
    for (int c = 0; c < C_CLS; ++c) {
        v[c] = g_logits[b * C_CLS + c];
        mx = fmaxf(mx, v[c]);
    }
    float s = 0.f;
#pragma unroll
    for (int c = 0; c < C_CLS; ++c) s += expf(v[c] - mx);
    float lg = mx + logf(s);
#pragma unroll
    for (int c = 0; c < C_CLS; ++c) out[b * C_CLS + c] = v[c] - lg;
}

// ---------------------------------------------------------------------------
// Entry point
// ---------------------------------------------------------------------------
extern "C" void kernel_launch(void* const* d_in, const int* in_sizes, int n_in,
                              void* d_out, int out_size) {
    const float* tensor  = (const float*)d_in[0];   // (2048, 1024)
    const float* w_first = (const float*)d_in[1];   // (10, 1, 4, 128)
    const float* w_mid   = (const float*)d_in[2];   // (10, 128, 4, 128)
    const float* w_last  = (const float*)d_in[3];   // (10, 128, 4, 1)
    float* out = (float*)d_out;                     // (2048, 10)

    cudaFuncSetAttribute(rec_fp8_kernel, cudaFuncAttributeMaxDynamicSharedMemorySize, SMEM_BYTES);

    feat_kernel<<<(B_FULL * T_DIV) / 256, 256>>>(tensor);
    rec_fp8_kernel<<<dim3(B_FULL / BT, C_CLS), NTHR, SMEM_BYTES>>>(w_first, w_mid, w_last);
    lsm_kernel<<<(B_FULL + 255) / 256, 256>>>(out);
}

// round 12
// speedup vs baseline: 1.0143x; 1.0143x over previous
#include <cuda_runtime.h>
#include <cuda_bf16.h>
#include <cuda_fp8.h>
#include <math.h>
#include <cstdint>

// ---------------------------------------------------------------------------
// Problem constants
// ---------------------------------------------------------------------------
namespace {
constexpr int B_FULL  = 2048;
constexpr int N_PIX   = 1024;
constexpr int T_DIV   = 64;
constexpr int C_CLS   = 10;
constexpr int PER_DIV = 16;
constexpr int K_DIM   = 512;          // k = i*4 + m (w_mid memory order)
constexpr int R_RANK  = 128;
constexpr int BT      = 64;           // batch rows per CTA
constexpr int NTHR    = 256;          // 8 warps: 2(m) x 4(n), warp tile m32 x n32
constexpr int NKT     = 16;           // k32 tiles total
constexpr int NBP     = 8;            // k32 tiles with B persistent in registers

constexpr int PADK8   = 528;          // fp8 row stride (bytes); 528 mod 128 = 16 -> conflict-free

// smem byte offsets
constexpr int OFF_B   = 0;                          // [128][528] fp8 = 67584
constexpr int OFF_A   = OFF_B + R_RANK * PADK8;     // [64][528] fp8 = 33792
constexpr int OFF_X   = OFF_A + BT * PADK8;         // 64 float4 = 1024
constexpr int OFF_S0  = OFF_X + 1024;               // 128 f32
constexpr int OFF_WL  = OFF_S0 + 512;               // 128 f32
constexpr int OFF_RED = OFF_WL + 512;               // 64*16 f32 = 4096
constexpr int OFF_MAX = OFF_RED + 4096;             // 8 f32
constexpr int SMEM_BYTES = OFF_MAX + 64;            // ~107 KB
}

// ---------------------------------------------------------------------------
// Device scratch
// ---------------------------------------------------------------------------
__device__ float4 g_div4[T_DIV * B_FULL];      // [t][b] -> M=4 features
__device__ float  g_logits[B_FULL * C_CLS];    // [b][c]

// ---------------------------------------------------------------------------
// asm helpers
// ---------------------------------------------------------------------------
__device__ __forceinline__ uint32_t smem_to_u32(const void* p) {
    uint32_t a;
    asm("{ .reg .u64 t; cvta.to.shared.u64 t, %1; cvt.u32.u64 %0, t; }" : "=r"(a) : "l"(p));
    return a;
}
__device__ __forceinline__ void ldsm4(uint32_t* r, uint32_t addr) {
    asm volatile("ldmatrix.sync.aligned.m8n8.x4.shared.b16 {%0,%1,%2,%3}, [%4];"
                 : "=r"(r[0]), "=r"(r[1]), "=r"(r[2]), "=r"(r[3]) : "r"(addr));
}
// fp8 e4m3 mma: m16n8k32, fp32 accumulate (sm_89+)
__device__ __forceinline__ void mma16832f8(float* d, const uint32_t* a, uint32_t b0, uint32_t b1) {
    asm volatile("mma.sync.aligned.m16n8k32.row.col.f32.e4m3.e4m3.f32 "
                 "{%0,%1,%2,%3}, {%4,%5,%6,%7}, {%8,%9}, {%0,%1,%2,%3};"
                 : "+f"(d[0]), "+f"(d[1]), "+f"(d[2]), "+f"(d[3])
                 : "r"(a[0]), "r"(a[1]), "r"(a[2]), "r"(a[3]), "r"(b0), "r"(b1));
}
// pack 4 floats into 4 e4m3 bytes (v0 = lowest byte)
__device__ __forceinline__ uint32_t pack4e4m3(float v0, float v1, float v2, float v3) {
    uint16_t h0, h1; uint32_t u;
    asm("cvt.rn.satfinite.e4m3x2.f32 %0, %1, %2;" : "=h"(h0) : "f"(v1), "f"(v0));
    asm("cvt.rn.satfinite.e4m3x2.f32 %0, %1, %2;" : "=h"(h1) : "f"(v3), "f"(v2));
    asm("mov.b32 %0, {%1, %2};" : "=r"(u) : "h"(h0), "h"(h1));
    return u;
}
__device__ __forceinline__ uint8_t f2e4m3(float v) {
    uint16_t h;
    asm("cvt.rn.satfinite.e4m3x2.f32 %0, %1, %2;" : "=h"(h) : "f"(0.f), "f"(v));
    return (uint8_t)(h & 0xFF);
}

// ---------------------------------------------------------------------------
// Kernel 1: feature map + division averaging
// ---------------------------------------------------------------------------
__global__ void feat_kernel(const float* __restrict__ tensor) {
    int idx = blockIdx.x * blockDim.x + threadIdx.x;
    if (idx >= B_FULL * T_DIV) return;
    int b = idx >> 6;
    int t = idx & (T_DIV - 1);
    const float4* p = reinterpret_cast<const float4*>(tensor + b * N_PIX + t * PER_DIV);
    float a0 = 0.f, a1 = 0.f, a2 = 0.f, a3 = 0.f;
#pragma unroll
    for (int j = 0; j < 4; ++j) {
        float4 v = p[j];
        float xs[4] = {v.x, v.y, v.z, v.w};
#pragma unroll
        for (int q = 0; q < 4; ++q) {
            float ang = 1.57079632679489662f * xs[q];
            float s, c;
            sincosf(ang, &s, &c);
            float c2 = c * c, s2 = s * s;
            a0 += c2 * c; a1 += c2 * s; a2 += c * s2; a3 += s2 * s;
        }
    }
    const float inv = 1.0f / (float)PER_DIV;
    g_div4[t * B_FULL + b] = make_float4(a0 * inv, a1 * inv, a2 * inv, a3 * inv);
}

// ---------------------------------------------------------------------------
// Kernel 2: TT recurrence via fp8 e4m3 mma (fp32 accum), R8 flat skeleton.
// B: NBP=8 k32-tiles persistent in registers, 8 double-buffered from SMEM
// (register budget kept ~180 to avoid the R11 spill).
// Exact scaling: B staged as W*2^8; A scaled 2^-e_t per step from tracked
// max|state| (exponent via bit ops); F = sum(8 - e_t); logits *= 2^-F.
// ---------------------------------------------------------------------------
__global__ __launch_bounds__(NTHR) void rec_fp8_kernel(const float* __restrict__ w_first,
                                                       const float* __restrict__ w_mid,
                                                       const float* __restrict__ w_last) {
    extern __shared__ char smem[];
    const int tid = threadIdx.x;
    const int l   = tid & 31;
    const int wid = tid >> 5;
    const int mg  = wid & 1;      // m-group: rows mg*32 .. +31
    const int ng  = wid >> 1;     // n-group: cols ng*32 .. +31
    const int c   = blockIdx.y;
    const int b0  = blockIdx.x * BT;

    const uint32_t smem_u = smem_to_u32(smem);
    float*  s0s  = reinterpret_cast<float*>(smem + OFF_S0);
    float*  wls  = reinterpret_cast<float*>(smem + OFF_WL);
    float4* sX   = reinterpret_cast<float4*>(smem + OFF_X);
    float*  sRed = reinterpret_cast<float*>(smem + OFF_RED);
    float*  sMax = reinterpret_cast<float*>(smem + OFF_MAX);

    // ---- stage B: fp8(W[k][o] * 256), row o, byte col k, stride 528 ----
    {
        const float* Wc = w_mid + c * (K_DIM * R_RANK);
        for (int q = tid; q < K_DIM * R_RANK / 4; q += NTHR) {
            int k = q >> 5;
            int j = (q & 31) << 2;
            float4 v = *reinterpret_cast<const float4*>(Wc + k * R_RANK + j);
            smem[OFF_B + (j + 0) * PADK8 + k] = (char)f2e4m3(v.x * 256.f);
            smem[OFF_B + (j + 1) * PADK8 + k] = (char)f2e4m3(v.y * 256.f);
            smem[OFF_B + (j + 2) * PADK8 + k] = (char)f2e4m3(v.z * 256.f);
            smem[OFF_B + (j + 3) * PADK8 + k] = (char)f2e4m3(v.w * 256.f);
        }
    }
    if (tid < R_RANK) {
        const float* wf = w_first + c * 512;
        s0s[tid] = wf[tid] + wf[128 + tid] + wf[256 + tid] + wf[384 + tid];
        const float* wl = w_last + c * 512;
        wls[tid] = wl[4 * tid] + wl[4 * tid + 1] + wl[4 * tid + 2] + wl[4 * tid + 3];
    }
    __syncthreads();

    // ldmatrix bases: 16-row x 32-fp8 tiles, canonical x4 mapping
    uint32_t aBase[2], bBase[2];
#pragma unroll
    for (int mt = 0; mt < 2; ++mt)
        aBase[mt] = smem_u + OFF_A +
            (mg * 32 + mt * 16 + (l & 7) + ((l >> 3) & 1) * 8) * PADK8 + (l >> 4) * 16;
#pragma unroll
    for (int p = 0; p < 2; ++p)
        bBase[p] = smem_u + OFF_B +
            (ng * 32 + p * 16 + (l >> 4) * 8 + (l & 7)) * PADK8 + ((l >> 3) & 1) * 16;

    // ---- persistent B for kt 0..NBP-1: 8 x 2 x 4 = 64 regs ----
    uint32_t Bp[NBP][2][4];
#pragma unroll
    for (int kt = 0; kt < NBP; ++kt) {
        ldsm4(Bp[kt][0], bBase[0] + kt * 32);
        ldsm4(Bp[kt][1], bBase[1] + kt * 32);
    }

    float acc[2][4][4];
    const int g  = l >> 2;
    const int cc = l & 3;
    int F = 0;                       // exact exponent ledger

    float4 gx = make_float4(0.f, 0.f, 0.f, 0.f);
    if (tid < BT) gx = g_div4[b0 + tid];

    for (int t = 0; t < T_DIV; ++t) {
        if (tid < BT) sX[tid] = gx;
        __syncthreads();   // sX/sMax ready; previous GEMM done with sA

        float ascale;
        int e;
        if (t == 0) {
            e = -5; ascale = 32.f;   // |s0| <~ 1.5 -> A max <~ 48
        } else {
            float mm = 1e-20f;
#pragma unroll
            for (int w = 0; w < 8; ++w) mm = fmaxf(mm, sMax[w]);
            // e = floor(log2(mm)) - 6 via exponent bits; ascale = 2^-e exactly
            e = ((int)(__float_as_uint(mm) >> 23) & 0xFF) - 127 - 6;
            ascale = __uint_as_float((uint32_t)(127 - e) << 23);
        }
        F += 8 - e;

        if (t == 0) {
            // A[b][4i+m] = e4m3(s0[i]*x[b][m]*32); thread owns i = tid&127
            int i  = tid & 127;
            int bh = tid >> 7;
            float s = s0s[i] * 32.f;
            for (int b = bh * 32; b < bh * 32 + 32; ++b) {
                float4 x = sX[b];
                *reinterpret_cast<uint32_t*>(smem + OFF_A + b * PADK8 + 4 * i) =
                    pack4e4m3(s * x.x, s * x.y, s * x.z, s * x.w);
            }
        } else {
            // convert this warp's D fragments into A (fp8, scaled)
#pragma unroll
            for (int mt = 0; mt < 2; ++mt) {
                int r = mg * 32 + mt * 16 + g;
                float4 xa = sX[r];
                float4 xb = sX[r + 8];
                float xa0 = xa.x * ascale, xa1 = xa.y * ascale, xa2 = xa.z * ascale, xa3 = xa.w * ascale;
                float xb0 = xb.x * ascale, xb1 = xb.y * ascale, xb2 = xb.z * ascale, xb3 = xb.w * ascale;
#pragma unroll
                for (int nt = 0; nt < 4; ++nt) {
                    int i0 = ng * 32 + nt * 8 + 2 * cc;
                    float c0 = acc[mt][nt][0], c1 = acc[mt][nt][1];
                    float c2 = acc[mt][nt][2], c3 = acc[mt][nt][3];
                    uint2 ua, ub;
                    ua.x = pack4e4m3(c0 * xa0, c0 * xa1, c0 * xa2, c0 * xa3);
                    ua.y = pack4e4m3(c1 * xa0, c1 * xa1, c1 * xa2, c1 * xa3);
                    *reinterpret_cast<uint2*>(smem + OFF_A + r * PADK8 + 4 * i0) = ua;
                    ub.x = pack4e4m3(c2 * xb0, c2 * xb1, c2 * xb2, c2 * xb3);
                    ub.y = pack4e4m3(c3 * xb0, c3 * xb1, c3 * xb2, c3 * xb3);
                    *reinterpret_cast<uint2*>(smem + OFF_A + (r + 8) * PADK8 + 4 * i0) = ub;
                }
            }
        }
#pragma unroll
        for (int mt = 0; mt < 2; ++mt)
#pragma unroll
            for (int nt = 0; nt < 4; ++nt)
#pragma unroll
                for (int q = 0; q < 4; ++q) acc[mt][nt][q] = 0.f;
        __syncthreads();   // sA fully built

        if (tid < BT && t + 1 < T_DIV) gx = g_div4[(t + 1) * B_FULL + b0 + tid];

        // ---- section 1 (kt < NBP): B from registers, A double-buffered ----
        uint32_t Af[2][2][4], Bf[2][2][4];
        ldsm4(Af[0][0], aBase[0]);
        ldsm4(Af[0][1], aBase[1]);
        ldsm4(Bf[NBP & 1][0], bBase[0] + NBP * 32);   // preload B for kt=NBP
        ldsm4(Bf[NBP & 1][1], bBase[1] + NBP * 32);
#pragma unroll
        for (int kt = 0; kt < NBP; ++kt) {
            int cur = kt & 1, nx = cur ^ 1;
            ldsm4(Af[nx][0], aBase[0] + (kt + 1) * 32);
            ldsm4(Af[nx][1], aBase[1] + (kt + 1) * 32);
#pragma unroll
            for (int nt = 0; nt < 4; ++nt) {
                uint32_t b0v = Bp[kt][nt >> 1][(nt & 1) * 2];
                uint32_t b1v = Bp[kt][nt >> 1][(nt & 1) * 2 + 1];
                mma16832f8(acc[0][nt], Af[cur][0], b0v, b1v);
                mma16832f8(acc[1][nt], Af[cur][1], b0v, b1v);
            }
        }
        // ---- section 2 (kt = NBP..15): A and B double-buffered ----
#pragma unroll
        for (int kt = NBP; kt < NKT; ++kt) {
            int cur = kt & 1, nx = cur ^ 1;
            if (kt < NKT - 1) {
                ldsm4(Af[nx][0], aBase[0] + (kt + 1) * 32);
                ldsm4(Af[nx][1], aBase[1] + (kt + 1) * 32);
                ldsm4(Bf[nx][0], bBase[0] + (kt + 1) * 32);
                ldsm4(Bf[nx][1], bBase[1] + (kt + 1) * 32);
            }
#pragma unroll
            for (int nt = 0; nt < 4; ++nt) {
                uint32_t b0v = Bf[cur][nt >> 1][(nt & 1) * 2];
                uint32_t b1v = Bf[cur][nt >> 1][(nt & 1) * 2 + 1];
                mma16832f8(acc[0][nt], Af[cur][0], b0v, b1v);
                mma16832f8(acc[1][nt], Af[cur][1], b0v, b1v);
            }
        }

        // per-warp max|state| for next step's exponent
        float m = 1e-20f;
#pragma unroll
        for (int mt = 0; mt < 2; ++mt)
#pragma unroll
            for (int nt = 0; nt < 4; ++nt)
#pragma unroll
                for (int q = 0; q < 4; ++q) m = fmaxf(m, fabsf(acc[mt][nt][q]));
#pragma unroll
        for (int off = 16; off; off >>= 1) m = fmaxf(m, __shfl_xor_sync(0xFFFFFFFFu, m, off));
        if (l == 0) sMax[wid] = m;
    }

    // ---- final projection: logits[b] = dot(state_b, wl) * 2^-F ----
#pragma unroll
    for (int mt = 0; mt < 2; ++mt) {
        int r = mg * 32 + mt * 16 + g;
        float p0 = 0.f, p1 = 0.f;
#pragma unroll
        for (int nt = 0; nt < 4; ++nt) {
            int i0 = ng * 32 + nt * 8 + 2 * cc;
            float w0 = wls[i0], w1 = wls[i0 + 1];
            p0 += acc[mt][nt][0] * w0 + acc[mt][nt][1] * w1;
            p1 += acc[mt][nt][2] * w0 + acc[mt][nt][3] * w1;
        }
        sRed[r * 16 + ng * 4 + cc]       = p0;
        sRed[(r + 8) * 16 + ng * 4 + cc] = p1;
    }
    __syncthreads();
    if (tid < BT) {
        float sum = 0.f;
#pragma unroll
        for (int q = 0; q < 16; ++q) sum += sRed[tid * 16 + q];
        g_logits[(b0 + tid) * C_CLS + c] = sum * exp2f((float)(-F));
    }
}

// ---------------------------------------------------------------------------
// Kernel 3: log_softmax over C=10
// ---------------------------------------------------------------------------
__global__ void lsm_kernel(float* __restrict__ out) {
    int b = blockIdx.x * blockDim.x + threadIdx.x;
    if (b >= B_FULL) return;
    float v[C_CLS];
    float mx = -INFINITY;
#pragma unroll
    for (int c = 0; c < C_CLS; ++c) {
        v[c] = g_logits[b * C_CLS + c];
        mx = fmaxf(mx, v[c]);
    }
    float s = 0.f;
#pragma unroll
    for (int c = 0; c < C_CLS; ++c) s += expf(v[c] - mx);
    float lg = mx + logf(s);
#pragma unroll
    for (int c = 0; c < C_CLS; ++c) out[b * C_CLS + c] = v[c] - lg;
}

// ---------------------------------------------------------------------------
// Entry point
// ---------------------------------------------------------------------------
extern "C" void kernel_launch(void* const* d_in, const int* in_sizes, int n_in,
                              void* d_out, int out_size) {
    const float* tensor  = (const float*)d_in[0];   // (2048, 1024)
    const float* w_first = (const float*)d_in[1];   // (10, 1, 4, 128)
    const float* w_mid   = (const float*)d_in[2];   // (10, 128, 4, 128)
    const float* w_last  = (const float*)d_in[3];   // (10, 128, 4, 1)
    float* out = (float*)d_out;                     // (2048, 10)

    cudaFuncSetAttribute(rec_fp8_kernel, cudaFuncAttributeMaxDynamicSharedMemorySize, SMEM_BYTES);

    feat_kernel<<<(B_FULL * T_DIV) / 256, 256>>>(tensor);
    rec_fp8_kernel<<<dim3(B_FULL / BT, C_CLS), NTHR, SMEM_BYTES>>>(w_first, w_mid, w_last);
    lsm_kernel<<<(B_FULL + 255) / 256, 256>>>(out);
}

// round 14
// speedup vs baseline: 1.2848x; 1.2667x over previous
#include <cuda_runtime.h>
#include <cuda_bf16.h>
#include <math.h>
#include <cstdint>

// ---------------------------------------------------------------------------
// Problem constants
// ---------------------------------------------------------------------------
namespace {
constexpr int B_FULL  = 2048;
constexpr int N_PIX   = 1024;
constexpr int T_DIV   = 64;
constexpr int C_CLS   = 10;
constexpr int PER_DIV = 16;
constexpr int K_DIM   = 512;          // k = i*4 + m (w_mid memory order)
constexpr int R_RANK  = 128;
constexpr int BT      = 64;           // batch rows per CTA
constexpr int NTHR    = 256;          // 8 warps: 2(m) x 4(n), warp tile m32 x n32
constexpr int NB      = 16;           // k-tiles whose B fragments persist in registers

constexpr int PADK    = 520;          // padded k-stride (halves) -> conflict-free ldmatrix

// smem byte offsets
constexpr int OFF_B   = 0;                         // [128][520] bf16 = 133120
constexpr int OFF_A   = OFF_B + R_RANK * PADK * 2; // [64][520] bf16 = 66560
constexpr int OFF_X   = OFF_A + BT * PADK * 2;     // 2 groups x 2 bufs x 32 float4 = 2048
constexpr int OFF_S0  = OFF_X + 2048;              // 128 f32
constexpr int OFF_WL  = OFF_S0 + 512;              // 128 f32
constexpr int OFF_RED = OFF_WL + 512;              // 64*16 f32 = 4096
constexpr int SMEM_BYTES = OFF_RED + 4096;         // 206848
}

// ---------------------------------------------------------------------------
// Device scratch
// ---------------------------------------------------------------------------
__device__ float4 g_div4[T_DIV * B_FULL];      // [t][b] -> M=4 features
__device__ float  g_logits[B_FULL * C_CLS];    // [b][c]

// ---------------------------------------------------------------------------
// asm helpers (base-sm_103 legal)
// ---------------------------------------------------------------------------
__device__ __forceinline__ uint32_t smem_to_u32(const void* p) {
    uint32_t a;
    asm("{ .reg .u64 t; cvta.to.shared.u64 t, %1; cvt.u32.u64 %0, t; }" : "=r"(a) : "l"(p));
    return a;
}
__device__ __forceinline__ void ldsm4(uint32_t* r, uint32_t addr) {
    asm volatile("ldmatrix.sync.aligned.m8n8.x4.shared.b16 {%0,%1,%2,%3}, [%4];"
                 : "=r"(r[0]), "=r"(r[1]), "=r"(r[2]), "=r"(r[3]) : "r"(addr));
}
__device__ __forceinline__ void mma16816(float* d, const uint32_t* a, uint32_t b0, uint32_t b1) {
    asm volatile("mma.sync.aligned.m16n8k16.row.col.f32.bf16.bf16.f32 "
                 "{%0,%1,%2,%3}, {%4,%5,%6,%7}, {%8,%9}, {%0,%1,%2,%3};"
                 : "+f"(d[0]), "+f"(d[1]), "+f"(d[2]), "+f"(d[3])
                 : "r"(a[0]), "r"(a[1]), "r"(a[2]), "r"(a[3]), "r"(b0), "r"(b1));
}
__device__ __forceinline__ uint32_t packbf(float hi, float lo) {
    uint32_t u;
    asm("cvt.rn.bf16x2.f32 %0, %1, %2;" : "=r"(u) : "f"(hi), "f"(lo));
    return u;   // memory order: [lo, hi]
}
__device__ __forceinline__ uint32_t mulbf2(uint32_t a, uint32_t b) {
    uint32_t d;
    asm("mul.bf16x2 %0, %1, %2;" : "=r"(d) : "r"(a), "r"(b));
    return d;
}
__device__ __forceinline__ void bar_sync128(int id) {
    asm volatile("bar.sync %0, 128;" :: "r"(id) : "memory");
}

// ---------------------------------------------------------------------------
// Kernel 1: feature map + division averaging
// ---------------------------------------------------------------------------
__global__ void feat_kernel(const float* __restrict__ tensor) {
    int idx = blockIdx.x * blockDim.x + threadIdx.x;
    if (idx >= B_FULL * T_DIV) return;
    int b = idx >> 6;
    int t = idx & (T_DIV - 1);
    const float4* p = reinterpret_cast<const float4*>(tensor + b * N_PIX + t * PER_DIV);
    float a0 = 0.f, a1 = 0.f, a2 = 0.f, a3 = 0.f;
#pragma unroll
    for (int j = 0; j < 4; ++j) {
        float4 v = p[j];
        float xs[4] = {v.x, v.y, v.z, v.w};
#pragma unroll
        for (int q = 0; q < 4; ++q) {
            float ang = 1.57079632679489662f * xs[q];
            float s, c;
            sincosf(ang, &s, &c);
            float c2 = c * c, s2 = s * s;
            a0 += c2 * c; a1 += c2 * s; a2 += c * s2; a3 += s2 * s;
        }
    }
    const float inv = 1.0f / (float)PER_DIV;
    g_div4[t * B_FULL + b] = make_float4(a0 * inv, a1 * inv, a2 * inv, a3 * inv);
}

// ---------------------------------------------------------------------------
// Kernel 2: TT recurrence via ldmatrix + mma.sync (bf16, fp32 accum).
// 8 warps, 2(m) x 4(n).  The CTA is split into two INDEPENDENT 128-thread
// halves by mg: warp (mg,ng)'s GEMM reads only A rows [mg*32,+32), which are
// built only by same-mg warps; B is read-only.  Each half uses its own
// named barrier (id 1+mg) and its own double-buffered 32-row x copy,
// written by its warp ng=0 during the previous GEMM phase.  The halves
// drift freely, overlapping one half's A-build with the other's tensor work.
// ---------------------------------------------------------------------------
__global__ __launch_bounds__(NTHR) void rec_hmma_kernel(const float* __restrict__ w_first,
                                                        const float* __restrict__ w_mid,
                                                        const float* __restrict__ w_last) {
    extern __shared__ char smem[];
    const int tid = threadIdx.x;
    const int l   = tid & 31;
    const int wid = tid >> 5;
    const int mg  = wid & 1;      // m-group: rows mg*32 .. +31
    const int ng  = wid >> 1;     // n-group: cols ng*32 .. +31
    const int c   = blockIdx.y;
    const int b0  = blockIdx.x * BT;

    const uint32_t smem_u = smem_to_u32(smem);
    __nv_bfloat16* sB = reinterpret_cast<__nv_bfloat16*>(smem + OFF_B);
    float*  s0s  = reinterpret_cast<float*>(smem + OFF_S0);
    float*  wls  = reinterpret_cast<float*>(smem + OFF_WL);
    float4 (*sXg)[32] = reinterpret_cast<float4 (*)[32]>(smem + OFF_X);  // [mg*2+buf][32]
    float*  sRed = reinterpret_cast<float*>(smem + OFF_RED);

    // ---- stage weights: sB[o][k] = bf16(w_mid[c, k, o]), padded stride ----
    {
        const float* Wc = w_mid + c * (K_DIM * R_RANK);
        for (int q = tid; q < K_DIM * R_RANK / 4; q += NTHR) {
            int k = q >> 5;
            int j = (q & 31) << 2;
            float4 v = *reinterpret_cast<const float4*>(Wc + k * R_RANK + j);
            sB[(j + 0) * PADK + k] = __float2bfloat16(v.x);
            sB[(j + 1) * PADK + k] = __float2bfloat16(v.y);
            sB[(j + 2) * PADK + k] = __float2bfloat16(v.z);
            sB[(j + 3) * PADK + k] = __float2bfloat16(v.w);
        }
    }
    if (tid < R_RANK) {
        const float* wf = w_first + c * 512;
        s0s[tid] = wf[tid] + wf[128 + tid] + wf[256 + tid] + wf[384 + tid];
        const float* wl = w_last + c * 512;
        wls[tid] = wl[4 * tid] + wl[4 * tid + 1] + wl[4 * tid + 2] + wl[4 * tid + 3];
    }
    // x(t=0) for both groups (warp 0 -> group 0, warp 1 -> group 1)
    if (wid < 2) sXg[wid * 2 + 0][l] = g_div4[b0 + wid * 32 + l];
    __syncthreads();

    // ldmatrix address bases (bytes), canonical x4 lane->row mapping
    uint32_t aBase[2], bBase[2];
#pragma unroll
    for (int mt = 0; mt < 2; ++mt)
        aBase[mt] = smem_u + OFF_A +
            (((mg * 32 + mt * 16 + (l & 7) + ((l >> 3) & 1) * 8) * PADK + (l >> 4) * 8) << 1);
#pragma unroll
    for (int p = 0; p < 2; ++p)
        bBase[p] = smem_u + OFF_B +
            (((ng * 32 + p * 16 + (l >> 4) * 8 + (l & 7)) * PADK + ((l >> 3) & 1) * 8) << 1);

    // ---- persistent B fragments for kt 0..NB-1 (B is step-invariant) ----
    uint32_t Bp[NB][2][4];
#pragma unroll
    for (int kt = 0; kt < NB; ++kt) {
        ldsm4(Bp[kt][0], bBase[0] + kt * 32);
        ldsm4(Bp[kt][1], bBase[1] + kt * 32);
    }

    float acc[2][4][4];
    const int g  = l >> 2;     // row within 8-group
    const int cc = l & 3;      // col pair selector
    const int barid = 1 + mg;

    auto zero_acc = [&]() {
#pragma unroll
        for (int mt = 0; mt < 2; ++mt)
#pragma unroll
            for (int nt = 0; nt < 4; ++nt)
#pragma unroll
                for (int q = 0; q < 4; ++q) acc[mt][nt][q] = 0.f;
    };
    // full 32-kt GEMM: section 1 B-from-regs, section 2 double-buffered
    auto gemm_step = [&]() {
        uint32_t Af[2][2][4], Bf[2][2][4];
        ldsm4(Af[0][0], aBase[0]);
        ldsm4(Af[0][1], aBase[1]);
        ldsm4(Bf[NB & 1][0], bBase[0] + NB * 32);
        ldsm4(Bf[NB & 1][1], bBase[1] + NB * 32);
#pragma unroll
        for (int kt = 0; kt < NB; ++kt) {
            int cur = kt & 1, nx = cur ^ 1;
            ldsm4(Af[nx][0], aBase[0] + (kt + 1) * 32);
            ldsm4(Af[nx][1], aBase[1] + (kt + 1) * 32);
#pragma unroll
            for (int nt = 0; nt < 4; ++nt) {
                uint32_t b0v = Bp[kt][nt >> 1][(nt & 1) * 2];
                uint32_t b1v = Bp[kt][nt >> 1][(nt & 1) * 2 + 1];
                mma16816(acc[0][nt], Af[cur][0], b0v, b1v);
                mma16816(acc[1][nt], Af[cur][1], b0v, b1v);
            }
        }
#pragma unroll
        for (int kt = NB; kt < 32; ++kt) {
            int cur = kt & 1, nx = cur ^ 1;
            if (kt < 31) {
                ldsm4(Af[nx][0], aBase[0] + (kt + 1) * 32);
                ldsm4(Af[nx][1], aBase[1] + (kt + 1) * 32);
                ldsm4(Bf[nx][0], bBase[0] + (kt + 1) * 32);
                ldsm4(Bf[nx][1], bBase[1] + (kt + 1) * 32);
            }
#pragma unroll
            for (int nt = 0; nt < 4; ++nt) {
                uint32_t b0v = Bf[cur][nt >> 1][(nt & 1) * 2];
                uint32_t b1v = Bf[cur][nt >> 1][(nt & 1) * 2 + 1];
                mma16816(acc[0][nt], Af[cur][0], b0v, b1v);
                mma16816(acc[1][nt], Af[cur][1], b0v, b1v);
            }
        }
    };

    // ---- t = 0: build full A from s0 (scattered threads), full sync --------
    {
        int i  = tid & 127;
        int bh = tid >> 7;
        float s = s0s[i];
        for (int b = bh * 32; b < bh * 32 + 32; ++b) {
            float4 x = sXg[(b >> 5) * 2 + 0][b & 31];
            uint2 u;
            u.x = packbf(s * x.y, s * x.x);
            u.y = packbf(s * x.w, s * x.z);
            *reinterpret_cast<uint2*>(smem + OFF_A + ((b * PADK + 4 * i) << 1)) = u;
        }
    }
    __syncthreads();
    zero_acc();
    if (wid < 2) sXg[wid * 2 + 1][l] = g_div4[1 * B_FULL + b0 + wid * 32 + l];  // x(t=1)
    gemm_step();

    // ---- steps t = 1 .. 63: two independent 128-thread halves --------------
    for (int t = 1; t < T_DIV; ++t) {
        bar_sync128(barid);   // group: prev GEMM done reading A half; sX(t) visible

        const float4* sXc = sXg[mg * 2 + (t & 1)];
#pragma unroll
        for (int mt = 0; mt < 2; ++mt) {
            int lr = mt * 16 + g;                 // local row in this mg half
            int r  = mg * 32 + lr;
            float4 xa = sXc[lr];
            float4 xb = sXc[lr + 8];
            uint32_t xa01 = packbf(xa.y, xa.x), xa23 = packbf(xa.w, xa.z);
            uint32_t xb01 = packbf(xb.y, xb.x), xb23 = packbf(xb.w, xb.z);
#pragma unroll
            for (int nt = 0; nt < 4; ++nt) {
                int i0 = ng * 32 + nt * 8 + 2 * cc;
                uint32_t s0p = packbf(acc[mt][nt][0], acc[mt][nt][0]);
                uint32_t s1p = packbf(acc[mt][nt][1], acc[mt][nt][1]);
                uint32_t s2p = packbf(acc[mt][nt][2], acc[mt][nt][2]);
                uint32_t s3p = packbf(acc[mt][nt][3], acc[mt][nt][3]);
                uint4 ua, ub;
                ua.x = mulbf2(s0p, xa01); ua.y = mulbf2(s0p, xa23);
                ua.z = mulbf2(s1p, xa01); ua.w = mulbf2(s1p, xa23);
                *reinterpret_cast<uint4*>(smem + OFF_A + ((r * PADK + 4 * i0) << 1)) = ua;
                ub.x = mulbf2(s2p, xb01); ub.y = mulbf2(s2p, xb23);
                ub.z = mulbf2(s3p, xb01); ub.w = mulbf2(s3p, xb23);
                *reinterpret_cast<uint4*>(smem + OFF_A + (((r + 8) * PADK + 4 * i0) << 1)) = ub;
            }
        }
        bar_sync128(barid);   // group: A half fully built

        zero_acc();
        if (wid < 2 && t + 1 < T_DIV)             // x(t+1) into the other buffer
            sXg[wid * 2 + ((t + 1) & 1)][l] = g_div4[(t + 1) * B_FULL + b0 + wid * 32 + l];
        gemm_step();
    }

    // ---- final projection: logits[b] = dot(state_b, wl) ----
#pragma unroll
    for (int mt = 0; mt < 2; ++mt) {
        int r = mg * 32 + mt * 16 + g;
        float p0 = 0.f, p1 = 0.f;
#pragma unroll
        for (int nt = 0; nt < 4; ++nt) {
            int i0 = ng * 32 + nt * 8 + 2 * cc;
            float w0 = wls[i0], w1 = wls[i0 + 1];
            p0 += acc[mt][nt][0] * w0 + acc[mt][nt][1] * w1;
            p1 += acc[mt][nt][2] * w0 + acc[mt][nt][3] * w1;
        }
        sRed[r * 16 + ng * 4 + cc]       = p0;
        sRed[(r + 8) * 16 + ng * 4 + cc] = p1;
    }
    __syncthreads();
    if (tid < BT) {
        float sum = 0.f;
#pragma unroll
        for (int q = 0; q < 16; ++q) sum += sRed[tid * 16 + q];
        g_logits[(b0 + tid) * C_CLS + c] = sum;
    }
}

// ---------------------------------------------------------------------------
// Kernel 3: log_softmax over C=10
// ---------------------------------------------------------------------------
__global__ void lsm_kernel(float* __restrict__ out) {
    int b = blockIdx.x * blockDim.x + threadIdx.x;
    if (b >= B_FULL) return;
    float v[C_CLS];
    float mx = -INFINITY;
#pragma unroll
    for (int c = 0; c < C_CLS; ++c) {
        v[c] = g_logits[b * C_CLS + c];
        mx = fmaxf(mx, v[c]);
    }
    float s = 0.f;
#pragma unroll
    for (int c = 0; c < C_CLS; ++c) s += expf(v[c] - mx);
    float lg = mx + logf(s);
#pragma unroll
    for (int c = 0; c < C_CLS; ++c) out[b * C_CLS + c] = v[c] - lg;
}

// ---------------------------------------------------------------------------
// Entry point
// ---------------------------------------------------------------------------
extern "C" void kernel_launch(void* const* d_in, const int* in_sizes, int n_in,
                              void* d_out, int out_size) {
    const float* tensor  = (const float*)d_in[0];   // (2048, 1024)
    const float* w_first = (const float*)d_in[1];   // (10, 1, 4, 128)
    const float* w_mid   = (const float*)d_in[2];   // (10, 128, 4, 128)
    const float* w_last  = (const float*)d_in[3];   // (10, 128, 4, 1)
    float* out = (float*)d_out;                     // (2048, 10)

    cudaFuncSetAttribute(rec_hmma_kernel, cudaFuncAttributeMaxDynamicSharedMemorySize, SMEM_BYTES);

    feat_kernel<<<(B_FULL * T_DIV) / 256, 256>>>(tensor);
    rec_hmma_kernel<<<dim3(B_FULL / BT, C_CLS), NTHR, SMEM_BYTES>>>(w_first, w_mid, w_last);
    lsm_kernel<<<(B_FULL + 255) / 256, 256>>>(out);
}

// round 15
// speedup vs baseline: 1.2896x; 1.0037x over previous
#include <cuda_runtime.h>
#include <cuda_bf16.h>
#include <math.h>
#include <cstdint>

// ---------------------------------------------------------------------------
// Problem constants
// ---------------------------------------------------------------------------
namespace {
constexpr int B_FULL  = 2048;
constexpr int N_PIX   = 1024;
constexpr int T_DIV   = 64;
constexpr int C_CLS   = 10;
constexpr int PER_DIV = 16;
constexpr int K_DIM   = 512;          // k = i*4 + m (w_mid memory order)
constexpr int R_RANK  = 128;
constexpr int BT      = 64;           // batch rows per CTA
constexpr int NTHR    = 256;          // 8 warps: 2(m) x 4(n), warp tile m32 x n32
constexpr int NB      = 16;           // k-tiles with B permanently in registers

constexpr int PADK    = 520;          // A row stride (halves); 1040 B mod 128 = 16 -> conflict-free
constexpr int PADB2   = 264;          // B2 row stride (halves); 528 B mod 128 = 16 -> conflict-free
constexpr int ABUF    = BT * PADK * 2;             // one A buffer = 66560 B

// smem byte offsets
constexpr int OFF_B2  = 0;                         // [128][264] bf16 (k 256..511) = 67584
constexpr int OFF_A   = OFF_B2 + R_RANK * PADB2 * 2; // 2 x [64][520] bf16 = 133120
constexpr int OFF_X   = OFF_A + 2 * ABUF;          // 2 groups x 2 bufs x 32 float4 = 2048
constexpr int OFF_S0  = OFF_X + 2048;              // 128 f32
constexpr int OFF_WL  = OFF_S0 + 512;              // 128 f32
constexpr int OFF_RED = OFF_WL + 512;              // 64*16 f32 = 4096
constexpr int SMEM_BYTES = OFF_RED + 4096;         // 207872
}

// ---------------------------------------------------------------------------
// Device scratch
// ---------------------------------------------------------------------------
__device__ float4 g_div4[T_DIV * B_FULL];      // [t][b] -> M=4 features
__device__ float  g_logits[B_FULL * C_CLS];    // [b][c]

// ---------------------------------------------------------------------------
// asm helpers (base-sm_103 legal)
// ---------------------------------------------------------------------------
__device__ __forceinline__ uint32_t smem_to_u32(const void* p) {
    uint32_t a;
    asm("{ .reg .u64 t; cvta.to.shared.u64 t, %1; cvt.u32.u64 %0, t; }" : "=r"(a) : "l"(p));
    return a;
}
__device__ __forceinline__ void ldsm4(uint32_t* r, uint32_t addr) {
    asm volatile("ldmatrix.sync.aligned.m8n8.x4.shared.b16 {%0,%1,%2,%3}, [%4];"
                 : "=r"(r[0]), "=r"(r[1]), "=r"(r[2]), "=r"(r[3]) : "r"(addr));
}
__device__ __forceinline__ void mma16816(float* d, const uint32_t* a, uint32_t b0, uint32_t b1) {
    asm volatile("mma.sync.aligned.m16n8k16.row.col.f32.bf16.bf16.f32 "
                 "{%0,%1,%2,%3}, {%4,%5,%6,%7}, {%8,%9}, {%0,%1,%2,%3};"
                 : "+f"(d[0]), "+f"(d[1]), "+f"(d[2]), "+f"(d[3])
                 : "r"(a[0]), "r"(a[1]), "r"(a[2]), "r"(a[3]), "r"(b0), "r"(b1));
}
__device__ __forceinline__ uint32_t packbf(float hi, float lo) {
    uint32_t u;
    asm("cvt.rn.bf16x2.f32 %0, %1, %2;" : "=r"(u) : "f"(hi), "f"(lo));
    return u;   // memory order: [lo, hi]
}
__device__ __forceinline__ uint32_t mulbf2(uint32_t a, uint32_t b) {
    uint32_t d;
    asm("mul.bf16x2 %0, %1, %2;" : "=r"(d) : "r"(a), "r"(b));
    return d;
}
__device__ __forceinline__ void bar_sync128(int id) {
    asm volatile("bar.sync %0, 128;" :: "r"(id) : "memory");
}

// ---------------------------------------------------------------------------
// Kernel 1: feature map + division averaging
// ---------------------------------------------------------------------------
__global__ void feat_kernel(const float* __restrict__ tensor) {
    int idx = blockIdx.x * blockDim.x + threadIdx.x;
    if (idx >= B_FULL * T_DIV) return;
    int b = idx >> 6;
    int t = idx & (T_DIV - 1);
    const float4* p = reinterpret_cast<const float4*>(tensor + b * N_PIX + t * PER_DIV);
    float a0 = 0.f, a1 = 0.f, a2 = 0.f, a3 = 0.f;
#pragma unroll
    for (int j = 0; j < 4; ++j) {
        float4 v = p[j];
        float xs[4] = {v.x, v.y, v.z, v.w};
#pragma unroll
        for (int q = 0; q < 4; ++q) {
            float ang = 1.57079632679489662f * xs[q];
            float s, c;
            sincosf(ang, &s, &c);
            float c2 = c * c, s2 = s * s;
            a0 += c2 * c; a1 += c2 * s; a2 += c * s2; a3 += s2 * s;
        }
    }
    const float inv = 1.0f / (float)PER_DIV;
    g_div4[t * B_FULL + b] = make_float4(a0 * inv, a1 * inv, a2 * inv, a3 * inv);
}

// ---------------------------------------------------------------------------
// Kernel 2: TT recurrence, bf16 mma.sync, split-CTA halves + double-buffered
// A + ONE barrier per step per half.  B kt0-15 in registers (staged once via
// the A region), kt16-31 in a compact smem array (stride 264 halves).
// ---------------------------------------------------------------------------
__global__ __launch_bounds__(NTHR) void rec_hmma_kernel(const float* __restrict__ w_first,
                                                        const float* __restrict__ w_mid,
                                                        const float* __restrict__ w_last) {
    extern __shared__ char smem[];
    const int tid = threadIdx.x;
    const int l   = tid & 31;
    const int wid = tid >> 5;
    const int mg  = wid & 1;      // m-group: rows mg*32 .. +31
    const int ng  = wid >> 1;     // n-group: cols ng*32 .. +31
    const int c   = blockIdx.y;
    const int b0  = blockIdx.x * BT;

    const uint32_t smem_u = smem_to_u32(smem);
    __nv_bfloat16* sB2 = reinterpret_cast<__nv_bfloat16*>(smem + OFF_B2);   // k 256..511
    __nv_bfloat16* sBt = reinterpret_cast<__nv_bfloat16*>(smem + OFF_A);    // temp: k 0..255, [128][520]
    float*  s0s  = reinterpret_cast<float*>(smem + OFF_S0);
    float*  wls  = reinterpret_cast<float*>(smem + OFF_WL);
    float4 (*sXg)[32] = reinterpret_cast<float4 (*)[32]>(smem + OFF_X);     // [mg*2+buf][32]
    float*  sRed = reinterpret_cast<float*>(smem + OFF_RED);

    // ---- stage weights: k<256 -> temp A region [o][520]; k>=256 -> sB2 ----
    {
        const float* Wc = w_mid + c * (K_DIM * R_RANK);
        for (int q = tid; q < K_DIM * R_RANK / 4; q += NTHR) {
            int k = q >> 5;
            int j = (q & 31) << 2;
            float4 v = *reinterpret_cast<const float4*>(Wc + k * R_RANK + j);
            if (k < 256) {
                sBt[(j + 0) * PADK + k] = __float2bfloat16(v.x);
                sBt[(j + 1) * PADK + k] = __float2bfloat16(v.y);
                sBt[(j + 2) * PADK + k] = __float2bfloat16(v.z);
                sBt[(j + 3) * PADK + k] = __float2bfloat16(v.w);
            } else {
                int kk = k - 256;
                sB2[(j + 0) * PADB2 + kk] = __float2bfloat16(v.x);
                sB2[(j + 1) * PADB2 + kk] = __float2bfloat16(v.y);
                sB2[(j + 2) * PADB2 + kk] = __float2bfloat16(v.z);
                sB2[(j + 3) * PADB2 + kk] = __float2bfloat16(v.w);
            }
        }
    }
    if (tid < R_RANK) {
        const float* wf = w_first + c * 512;
        s0s[tid] = wf[tid] + wf[128 + tid] + wf[256 + tid] + wf[384 + tid];
        const float* wl = w_last + c * 512;
        wls[tid] = wl[4 * tid] + wl[4 * tid + 1] + wl[4 * tid + 2] + wl[4 * tid + 3];
    }
    if (wid < 2) sXg[wid * 2 + 0][l] = g_div4[b0 + wid * 32 + l];   // x(0)
    __syncthreads();

    // ldmatrix bases, canonical x4 lane->row mapping
    uint32_t aBase[2], bBase2[2], bBaseT[2];
#pragma unroll
    for (int mt = 0; mt < 2; ++mt)
        aBase[mt] = smem_u + OFF_A +
            (((mg * 32 + mt * 16 + (l & 7) + ((l >> 3) & 1) * 8) * PADK + (l >> 4) * 8) << 1);
#pragma unroll
    for (int p = 0; p < 2; ++p) {
        int row = ng * 32 + p * 16 + (l >> 4) * 8 + (l & 7);
        bBase2[p] = smem_u + OFF_B2 + ((row * PADB2 + ((l >> 3) & 1) * 8) << 1);
        bBaseT[p] = smem_u + OFF_A  + ((row * PADK  + ((l >> 3) & 1) * 8) << 1);
    }

    // ---- persistent B fragments for kt 0..15 (from temp region) ----
    uint32_t Bp[NB][2][4];
#pragma unroll
    for (int kt = 0; kt < NB; ++kt) {
        ldsm4(Bp[kt][0], bBaseT[0] + kt * 32);
        ldsm4(Bp[kt][1], bBaseT[1] + kt * 32);
    }
    __syncthreads();   // all Bp loads done before A builds overwrite temp region

    float acc[2][4][4];
    const int g  = l >> 2;     // row within 8-group
    const int cc = l & 3;      // col pair selector
    const int barid = 1 + mg;

    auto zero_acc = [&]() {
#pragma unroll
        for (int mt = 0; mt < 2; ++mt)
#pragma unroll
            for (int nt = 0; nt < 4; ++nt)
#pragma unroll
                for (int q = 0; q < 4; ++q) acc[mt][nt][q] = 0.f;
    };
    // 32-kt GEMM on A buffer at byte offset aOff; kt<16 B from regs, rest from sB2
    auto gemm_step = [&](uint32_t aOff) {
        uint32_t Af[2][2][4], Bf[2][2][4];
        ldsm4(Af[0][0], aBase[0] + aOff);
        ldsm4(Af[0][1], aBase[1] + aOff);
        ldsm4(Bf[0][0], bBase2[0]);           // kt=16 preload (16&1==0)
        ldsm4(Bf[0][1], bBase2[1]);
#pragma unroll
        for (int kt = 0; kt < NB; ++kt) {
            int cur = kt & 1, nx = cur ^ 1;
            ldsm4(Af[nx][0], aBase[0] + aOff + (kt + 1) * 32);
            ldsm4(Af[nx][1], aBase[1] + aOff + (kt + 1) * 32);
#pragma unroll
            for (int nt = 0; nt < 4; ++nt) {
                uint32_t b0v = Bp[kt][nt >> 1][(nt & 1) * 2];
                uint32_t b1v = Bp[kt][nt >> 1][(nt & 1) * 2 + 1];
                mma16816(acc[0][nt], Af[cur][0], b0v, b1v);
                mma16816(acc[1][nt], Af[cur][1], b0v, b1v);
            }
        }
#pragma unroll
        for (int kt = NB; kt < 32; ++kt) {
            int cur = kt & 1, nx = cur ^ 1;
            if (kt < 31) {
                ldsm4(Af[nx][0], aBase[0] + aOff + (kt + 1) * 32);
                ldsm4(Af[nx][1], aBase[1] + aOff + (kt + 1) * 32);
                ldsm4(Bf[nx][0], bBase2[0] + (kt - 15) * 32);
                ldsm4(Bf[nx][1], bBase2[1] + (kt - 15) * 32);
            }
#pragma unroll
            for (int nt = 0; nt < 4; ++nt) {
                uint32_t b0v = Bf[cur][nt >> 1][(nt & 1) * 2];
                uint32_t b1v = Bf[cur][nt >> 1][(nt & 1) * 2 + 1];
                mma16816(acc[0][nt], Af[cur][0], b0v, b1v);
                mma16816(acc[1][nt], Af[cur][1], b0v, b1v);
            }
        }
    };

    float4 gxn = make_float4(0.f, 0.f, 0.f, 0.f);
    if (wid < 2) gxn = g_div4[1 * B_FULL + b0 + wid * 32 + l];      // x(1) in regs

    // ---- t = 0: build full A(0) from s0 into buf0, full sync ---------------
    {
        int i  = tid & 127;
        int bh = tid >> 7;
        float s = s0s[i];
        for (int b = bh * 32; b < bh * 32 + 32; ++b) {
            float4 x = sXg[(b >> 5) * 2 + 0][b & 31];
            uint2 u;
            u.x = packbf(s * x.y, s * x.x);
            u.y = packbf(s * x.w, s * x.z);
            *reinterpret_cast<uint2*>(smem + OFF_A + ((b * PADK + 4 * i) << 1)) = u;
        }
        if (wid < 2) sXg[wid * 2 + 1][l] = gxn;                      // x(1) -> buf1
    }
    __syncthreads();
    zero_acc();
    if (wid < 2) gxn = g_div4[2 * B_FULL + b0 + wid * 32 + l];       // x(2)
    gemm_step(0);

    // ---- steps t = 1 .. 63: one barrier per step per half ------------------
    for (int t = 1; t < T_DIV; ++t) {
        const uint32_t aOff = (uint32_t)(t & 1) * ABUF;
        const float4* sXc = sXg[mg * 2 + (t & 1)];

        // build OWN A block into buf t&1 (other warps may still be in GEMM(t-1)
        // reading buf (t-1)&1 -- disjoint buffer, safe)
#pragma unroll
        for (int mt = 0; mt < 2; ++mt) {
            int lr = mt * 16 + g;
            int r  = mg * 32 + lr;
            float4 xa = sXc[lr];
            float4 xb = sXc[lr + 8];
            uint32_t xa01 = packbf(xa.y, xa.x), xa23 = packbf(xa.w, xa.z);
            uint32_t xb01 = packbf(xb.y, xb.x), xb23 = packbf(xb.w, xb.z);
#pragma unroll
            for (int nt = 0; nt < 4; ++nt) {
                int i0 = ng * 32 + nt * 8 + 2 * cc;
                uint32_t s0p = packbf(acc[mt][nt][0], acc[mt][nt][0]);
                uint32_t s1p = packbf(acc[mt][nt][1], acc[mt][nt][1]);
                uint32_t s2p = packbf(acc[mt][nt][2], acc[mt][nt][2]);
                uint32_t s3p = packbf(acc[mt][nt][3], acc[mt][nt][3]);
                uint4 ua, ub;
                ua.x = mulbf2(s0p, xa01); ua.y = mulbf2(s0p, xa23);
                ua.z = mulbf2(s1p, xa01); ua.w = mulbf2(s1p, xa23);
                *reinterpret_cast<uint4*>(smem + OFF_A + aOff + ((r * PADK + 4 * i0) << 1)) = ua;
                ub.x = mulbf2(s2p, xb01); ub.y = mulbf2(s2p, xb23);
                ub.z = mulbf2(s3p, xb01); ub.w = mulbf2(s3p, xb23);
                *reinterpret_cast<uint4*>(smem + OFF_A + aOff + (((r + 8) * PADK + 4 * i0) << 1)) = ub;
            }
        }
        if (wid < 2 && t + 1 < T_DIV) sXg[wid * 2 + ((t + 1) & 1)][l] = gxn;  // STS only

        bar_sync128(barid);    // half: A(t) fully built; orders x STS too

        zero_acc();
        if (wid < 2 && t + 2 < T_DIV) gxn = g_div4[(t + 2) * B_FULL + b0 + wid * 32 + l];
        gemm_step(aOff);
    }

    // ---- final projection: logits[b] = dot(state_b, wl) ----
#pragma unroll
    for (int mt = 0; mt < 2; ++mt) {
        int r = mg * 32 + mt * 16 + g;
        float p0 = 0.f, p1 = 0.f;
#pragma unroll
        for (int nt = 0; nt < 4; ++nt) {
            int i0 = ng * 32 + nt * 8 + 2 * cc;
            float w0 = wls[i0], w1 = wls[i0 + 1];
            p0 += acc[mt][nt][0] * w0 + acc[mt][nt][1] * w1;
            p1 += acc[mt][nt][2] * w0 + acc[mt][nt][3] * w1;
        }
        sRed[r * 16 + ng * 4 + cc]       = p0;
        sRed[(r + 8) * 16 + ng * 4 + cc] = p1;
    }
    __syncthreads();
    if (tid < BT) {
        float sum = 0.f;
#pragma unroll
        for (int q = 0; q < 16; ++q) sum += sRed[tid * 16 + q];
        g_logits[(b0 + tid) * C_CLS + c] = sum;
    }
}

// ---------------------------------------------------------------------------
// Kernel 3: log_softmax over C=10
// ---------------------------------------------------------------------------
__global__ void lsm_kernel(float* __restrict__ out) {
    int b = blockIdx.x * blockDim.x + threadIdx.x;
    if (b >= B_FULL) return;
    float v[C_CLS];
    float mx = -INFINITY;
#pragma unroll
    for (int c = 0; c < C_CLS; ++c) {
        v[c] = g_logits[b * C_CLS + c];
        mx = fmaxf(mx, v[c]);
    }
    float s = 0.f;
#pragma unroll
    for (int c = 0; c < C_CLS; ++c) s += expf(v[c] - mx);
    float lg = mx + logf(s);
#pragma unroll
    for (int c = 0; c < C_CLS; ++c) out[b * C_CLS + c] = v[c] - lg;
}

// ---------------------------------------------------------------------------
// Entry point
// ---------------------------------------------------------------------------
extern "C" void kernel_launch(void* const* d_in, const int* in_sizes, int n_in,
                              void* d_out, int out_size) {
    const float* tensor  = (const float*)d_in[0];   // (2048, 1024)
    const float* w_first = (const float*)d_in[1];   // (10, 1, 4, 128)
    const float* w_mid   = (const float*)d_in[2];   // (10, 128, 4, 128)
    const float* w_last  = (const float*)d_in[3];   // (10, 128, 4, 1)
    float* out = (float*)d_out;                     // (2048, 10)

    cudaFuncSetAttribute(rec_hmma_kernel, cudaFuncAttributeMaxDynamicSharedMemorySize, SMEM_BYTES);

    feat_kernel<<<(B_FULL * T_DIV) / 256, 256>>>(tensor);
    rec_hmma_kernel<<<dim3(B_FULL / BT, C_CLS), NTHR, SMEM_BYTES>>>(w_first, w_mid, w_last);
    lsm_kernel<<<(B_FULL + 255) / 256, 256>>>(out);
}

// round 16
// speedup vs baseline: 1.4494x; 1.1239x over previous
#include <cuda_runtime.h>
#include <cuda_bf16.h>
#include <math.h>
#include <cstdint>

// ---------------------------------------------------------------------------
// Problem constants
// ---------------------------------------------------------------------------
namespace {
constexpr int B_FULL  = 2048;
constexpr int N_PIX   = 1024;
constexpr int T_DIV   = 64;
constexpr int C_CLS   = 10;
constexpr int PER_DIV = 16;
constexpr int K_DIM   = 512;          // k = i*4 + m (w_mid memory order)
constexpr int R_RANK  = 128;
constexpr int NTHR    = 256;
constexpr int NB      = 16;           // k-tiles with B permanently in registers

constexpr int PADK    = 520;          // A row stride (halves)
constexpr int PADB2   = 264;          // B2 row stride (halves)
constexpr int ABUF    = 64 * PADK * 2;             // big A buffer = 66560 B
constexpr int ABUF_S  = 32 * PADK * 2;             // small A buffer = 33280 B

// smem byte offsets
constexpr int OFF_B2  = 0;                           // [128][264] bf16 (k 256..511)
constexpr int OFF_A   = OFF_B2 + R_RANK * PADB2 * 2; // 133120 B region (A bufs / temp B)
constexpr int OFF_X   = OFF_A + 2 * ABUF;            // 4 x 32 float4 = 2048
constexpr int OFF_S0  = OFF_X + 2048;
constexpr int OFF_WL  = OFF_S0 + 512;
constexpr int OFF_RED = OFF_WL + 512;                // 4096 B
constexpr int SMEM_BYTES = OFF_RED + 4096;           // 207872

// task split: 296 big (BT=64) + 48 small (BT=32)
constexpr int N_BIG   = 296;
constexpr int N_GRID  = 344;
}

// ---------------------------------------------------------------------------
// Device scratch
// ---------------------------------------------------------------------------
__device__ float4 g_div4[T_DIV * B_FULL];      // [t][b] -> M=4 features
__device__ float  g_logits[B_FULL * C_CLS];    // [b][c]

// ---------------------------------------------------------------------------
// asm helpers
// ---------------------------------------------------------------------------
__device__ __forceinline__ uint32_t smem_to_u32(const void* p) {
    uint32_t a;
    asm("{ .reg .u64 t; cvta.to.shared.u64 t, %1; cvt.u32.u64 %0, t; }" : "=r"(a) : "l"(p));
    return a;
}
__device__ __forceinline__ void ldsm4(uint32_t* r, uint32_t addr) {
    asm volatile("ldmatrix.sync.aligned.m8n8.x4.shared.b16 {%0,%1,%2,%3}, [%4];"
                 : "=r"(r[0]), "=r"(r[1]), "=r"(r[2]), "=r"(r[3]) : "r"(addr));
}
__device__ __forceinline__ void mma16816(float* d, const uint32_t* a, uint32_t b0, uint32_t b1) {
    asm volatile("mma.sync.aligned.m16n8k16.row.col.f32.bf16.bf16.f32 "
                 "{%0,%1,%2,%3}, {%4,%5,%6,%7}, {%8,%9}, {%0,%1,%2,%3};"
                 : "+f"(d[0]), "+f"(d[1]), "+f"(d[2]), "+f"(d[3])
                 : "r"(a[0]), "r"(a[1]), "r"(a[2]), "r"(a[3]), "r"(b0), "r"(b1));
}
__device__ __forceinline__ uint32_t packbf(float hi, float lo) {
    uint32_t u;
    asm("cvt.rn.bf16x2.f32 %0, %1, %2;" : "=r"(u) : "f"(hi), "f"(lo));
    return u;
}
__device__ __forceinline__ uint32_t mulbf2(uint32_t a, uint32_t b) {
    uint32_t d;
    asm("mul.bf16x2 %0, %1, %2;" : "=r"(d) : "r"(a), "r"(b));
    return d;
}
__device__ __forceinline__ void bar_sync128(int id) {
    asm volatile("bar.sync %0, 128;" :: "r"(id) : "memory");
}

// ---------------------------------------------------------------------------
// Kernel 1: feature map + division averaging
// ---------------------------------------------------------------------------
__global__ void feat_kernel(const float* __restrict__ tensor) {
    int idx = blockIdx.x * blockDim.x + threadIdx.x;
    if (idx >= B_FULL * T_DIV) return;
    int b = idx >> 6;
    int t = idx & (T_DIV - 1);
    const float4* p = reinterpret_cast<const float4*>(tensor + b * N_PIX + t * PER_DIV);
    float a0 = 0.f, a1 = 0.f, a2 = 0.f, a3 = 0.f;
#pragma unroll
    for (int j = 0; j < 4; ++j) {
        float4 v = p[j];
        float xs[4] = {v.x, v.y, v.z, v.w};
#pragma unroll
        for (int q = 0; q < 4; ++q) {
            float ang = 1.57079632679489662f * xs[q];
            float s, c;
            sincosf(ang, &s, &c);
            float c2 = c * c, s2 = s * s;
            a0 += c2 * c; a1 += c2 * s; a2 += c * s2; a3 += s2 * s;
        }
    }
    const float inv = 1.0f / (float)PER_DIV;
    g_div4[t * B_FULL + b] = make_float4(a0 * inv, a1 * inv, a2 * inv, a3 * inv);
}

// ---------------------------------------------------------------------------
// Kernel 2: TT recurrence, bf16 mma.sync.  Mixed task sizes to kill wave
// quantization: bid<296 -> BT=64 task (R15 split-half skeleton); bid>=296
// -> BT=32 task (class 9 rows 512+, 8 warps m32 x n16, one syncthreads/step).
// ---------------------------------------------------------------------------
__global__ __launch_bounds__(NTHR) void rec_hmma_kernel(const float* __restrict__ w_first,
                                                        const float* __restrict__ w_mid,
                                                        const float* __restrict__ w_last) {
    extern __shared__ char smem[];
    const int tid = threadIdx.x;
    const int l   = tid & 31;
    const int wid = tid >> 5;
    const int bid = blockIdx.x;
    const bool big = (bid < N_BIG);
    const int c  = big ? (bid >> 5) : 9;
    const int b0 = big ? ((bid & 31) * 64) : (512 + (bid - N_BIG) * 32);

    const uint32_t smem_u = smem_to_u32(smem);
    __nv_bfloat16* sB2 = reinterpret_cast<__nv_bfloat16*>(smem + OFF_B2);
    __nv_bfloat16* sBt = reinterpret_cast<__nv_bfloat16*>(smem + OFF_A);   // temp staging
    float*  s0s  = reinterpret_cast<float*>(smem + OFF_S0);
    float*  wls  = reinterpret_cast<float*>(smem + OFF_WL);
    float4 (*sXg)[32] = reinterpret_cast<float4 (*)[32]>(smem + OFF_X);
    float*  sRed = reinterpret_cast<float*>(smem + OFF_RED);

    // ---- stage weights: k<256 -> temp A region; k>=256 -> sB2 ----
    {
        const float* Wc = w_mid + c * (K_DIM * R_RANK);
        for (int q = tid; q < K_DIM * R_RANK / 4; q += NTHR) {
            int k = q >> 5;
            int j = (q & 31) << 2;
            float4 v = *reinterpret_cast<const float4*>(Wc + k * R_RANK + j);
            if (k < 256) {
                sBt[(j + 0) * PADK + k] = __float2bfloat16(v.x);
                sBt[(j + 1) * PADK + k] = __float2bfloat16(v.y);
                sBt[(j + 2) * PADK + k] = __float2bfloat16(v.z);
                sBt[(j + 3) * PADK + k] = __float2bfloat16(v.w);
            } else {
                int kk = k - 256;
                sB2[(j + 0) * PADB2 + kk] = __float2bfloat16(v.x);
                sB2[(j + 1) * PADB2 + kk] = __float2bfloat16(v.y);
                sB2[(j + 2) * PADB2 + kk] = __float2bfloat16(v.z);
                sB2[(j + 3) * PADB2 + kk] = __float2bfloat16(v.w);
            }
        }
    }
    if (tid < R_RANK) {
        const float* wf = w_first + c * 512;
        s0s[tid] = wf[tid] + wf[128 + tid] + wf[256 + tid] + wf[384 + tid];
        const float* wl = w_last + c * 512;
        wls[tid] = wl[4 * tid] + wl[4 * tid + 1] + wl[4 * tid + 2] + wl[4 * tid + 3];
    }
    const int g  = l >> 2;
    const int cc = l & 3;

    if (big) {
        // =================== BT = 64 path (R15 skeleton) =====================
        const int mg  = wid & 1;
        const int ng  = wid >> 1;
        if (wid < 2) sXg[wid * 2 + 0][l] = g_div4[b0 + wid * 32 + l];
        __syncthreads();

        uint32_t aBase[2], bBase2[2], bBaseT[2];
#pragma unroll
        for (int mt = 0; mt < 2; ++mt)
            aBase[mt] = smem_u + OFF_A +
                (((mg * 32 + mt * 16 + (l & 7) + ((l >> 3) & 1) * 8) * PADK + (l >> 4) * 8) << 1);
#pragma unroll
        for (int p = 0; p < 2; ++p) {
            int row = ng * 32 + p * 16 + (l >> 4) * 8 + (l & 7);
            bBase2[p] = smem_u + OFF_B2 + ((row * PADB2 + ((l >> 3) & 1) * 8) << 1);
            bBaseT[p] = smem_u + OFF_A  + ((row * PADK  + ((l >> 3) & 1) * 8) << 1);
        }

        uint32_t Bp[NB][2][4];
#pragma unroll
        for (int kt = 0; kt < NB; ++kt) {
            ldsm4(Bp[kt][0], bBaseT[0] + kt * 32);
            ldsm4(Bp[kt][1], bBaseT[1] + kt * 32);
        }
        __syncthreads();

        float acc[2][4][4];
        const int barid = 1 + mg;

        auto zero_acc = [&]() {
#pragma unroll
            for (int mt = 0; mt < 2; ++mt)
#pragma unroll
                for (int nt = 0; nt < 4; ++nt)
#pragma unroll
                    for (int q = 0; q < 4; ++q) acc[mt][nt][q] = 0.f;
        };
        auto gemm_step = [&](uint32_t aOff) {
            uint32_t Af[2][2][4], Bf[2][2][4];
            ldsm4(Af[0][0], aBase[0] + aOff);
            ldsm4(Af[0][1], aBase[1] + aOff);
            ldsm4(Bf[0][0], bBase2[0]);
            ldsm4(Bf[0][1], bBase2[1]);
#pragma unroll
            for (int kt = 0; kt < NB; ++kt) {
                int cur = kt & 1, nx = cur ^ 1;
                ldsm4(Af[nx][0], aBase[0] + aOff + (kt + 1) * 32);
                ldsm4(Af[nx][1], aBase[1] + aOff + (kt + 1) * 32);
#pragma unroll
                for (int nt = 0; nt < 4; ++nt) {
                    uint32_t b0v = Bp[kt][nt >> 1][(nt & 1) * 2];
                    uint32_t b1v = Bp[kt][nt >> 1][(nt & 1) * 2 + 1];
                    mma16816(acc[0][nt], Af[cur][0], b0v, b1v);
                    mma16816(acc[1][nt], Af[cur][1], b0v, b1v);
                }
            }
#pragma unroll
            for (int kt = NB; kt < 32; ++kt) {
                int cur = kt & 1, nx = cur ^ 1;
                if (kt < 31) {
                    ldsm4(Af[nx][0], aBase[0] + aOff + (kt + 1) * 32);
                    ldsm4(Af[nx][1], aBase[1] + aOff + (kt + 1) * 32);
                    ldsm4(Bf[nx][0], bBase2[0] + (kt - 15) * 32);
                    ldsm4(Bf[nx][1], bBase2[1] + (kt - 15) * 32);
                }
#pragma unroll
                for (int nt = 0; nt < 4; ++nt) {
                    uint32_t b0v = Bf[cur][nt >> 1][(nt & 1) * 2];
                    uint32_t b1v = Bf[cur][nt >> 1][(nt & 1) * 2 + 1];
                    mma16816(acc[0][nt], Af[cur][0], b0v, b1v);
                    mma16816(acc[1][nt], Af[cur][1], b0v, b1v);
                }
            }
        };

        float4 gxn = make_float4(0.f, 0.f, 0.f, 0.f);
        if (wid < 2) gxn = g_div4[1 * B_FULL + b0 + wid * 32 + l];

        {
            int i  = tid & 127;
            int bh = tid >> 7;
            float s = s0s[i];
            for (int b = bh * 32; b < bh * 32 + 32; ++b) {
                float4 x = sXg[(b >> 5) * 2 + 0][b & 31];
                uint2 u;
                u.x = packbf(s * x.y, s * x.x);
                u.y = packbf(s * x.w, s * x.z);
                *reinterpret_cast<uint2*>(smem + OFF_A + ((b * PADK + 4 * i) << 1)) = u;
            }
            if (wid < 2) sXg[wid * 2 + 1][l] = gxn;
        }
        __syncthreads();
        zero_acc();
        if (wid < 2) gxn = g_div4[2 * B_FULL + b0 + wid * 32 + l];
        gemm_step(0);

        for (int t = 1; t < T_DIV; ++t) {
            const uint32_t aOff = (uint32_t)(t & 1) * ABUF;
            const float4* sXc = sXg[mg * 2 + (t & 1)];
#pragma unroll
            for (int mt = 0; mt < 2; ++mt) {
                int lr = mt * 16 + g;
                int r  = mg * 32 + lr;
                float4 xa = sXc[lr];
                float4 xb = sXc[lr + 8];
                uint32_t xa01 = packbf(xa.y, xa.x), xa23 = packbf(xa.w, xa.z);
                uint32_t xb01 = packbf(xb.y, xb.x), xb23 = packbf(xb.w, xb.z);
#pragma unroll
                for (int nt = 0; nt < 4; ++nt) {
                    int i0 = ng * 32 + nt * 8 + 2 * cc;
                    uint32_t s0p = packbf(acc[mt][nt][0], acc[mt][nt][0]);
                    uint32_t s1p = packbf(acc[mt][nt][1], acc[mt][nt][1]);
                    uint32_t s2p = packbf(acc[mt][nt][2], acc[mt][nt][2]);
                    uint32_t s3p = packbf(acc[mt][nt][3], acc[mt][nt][3]);
                    uint4 ua, ub;
                    ua.x = mulbf2(s0p, xa01); ua.y = mulbf2(s0p, xa23);
                    ua.z = mulbf2(s1p, xa01); ua.w = mulbf2(s1p, xa23);
                    *reinterpret_cast<uint4*>(smem + OFF_A + aOff + ((r * PADK + 4 * i0) << 1)) = ua;
                    ub.x = mulbf2(s2p, xb01); ub.y = mulbf2(s2p, xb23);
                    ub.z = mulbf2(s3p, xb01); ub.w = mulbf2(s3p, xb23);
                    *reinterpret_cast<uint4*>(smem + OFF_A + aOff + (((r + 8) * PADK + 4 * i0) << 1)) = ub;
                }
            }
            if (wid < 2 && t + 1 < T_DIV) sXg[wid * 2 + ((t + 1) & 1)][l] = gxn;

            bar_sync128(barid);

            zero_acc();
            if (wid < 2 && t + 2 < T_DIV) gxn = g_div4[(t + 2) * B_FULL + b0 + wid * 32 + l];
            gemm_step(aOff);
        }

#pragma unroll
        for (int mt = 0; mt < 2; ++mt) {
            int r = mg * 32 + mt * 16 + g;
            float p0 = 0.f, p1 = 0.f;
#pragma unroll
            for (int nt = 0; nt < 4; ++nt) {
                int i0 = ng * 32 + nt * 8 + 2 * cc;
                float w0 = wls[i0], w1 = wls[i0 + 1];
                p0 += acc[mt][nt][0] * w0 + acc[mt][nt][1] * w1;
                p1 += acc[mt][nt][2] * w0 + acc[mt][nt][3] * w1;
            }
            sRed[r * 16 + ng * 4 + cc]       = p0;
            sRed[(r + 8) * 16 + ng * 4 + cc] = p1;
        }
        __syncthreads();
        if (tid < 64) {
            float sum = 0.f;
#pragma unroll
            for (int q = 0; q < 16; ++q) sum += sRed[tid * 16 + q];
            g_logits[(b0 + tid) * C_CLS + c] = sum;
        }
    } else {
        // =================== BT = 32 path (8 warps, m32 x n16) ===============
        if (wid == 0) sXg[0][l] = g_div4[b0 + l];
        __syncthreads();

        uint32_t aBaseS[2], bBase2S, bBaseTS;
#pragma unroll
        for (int mt = 0; mt < 2; ++mt)
            aBaseS[mt] = smem_u + OFF_A +
                (((mt * 16 + (l & 7) + ((l >> 3) & 1) * 8) * PADK + (l >> 4) * 8) << 1);
        {
            int row = wid * 16 + (l >> 4) * 8 + (l & 7);
            bBase2S = smem_u + OFF_B2 + ((row * PADB2 + ((l >> 3) & 1) * 8) << 1);
            bBaseTS = smem_u + OFF_A  + ((row * PADK  + ((l >> 3) & 1) * 8) << 1);
        }

        uint32_t BpS[NB][4];
#pragma unroll
        for (int kt = 0; kt < NB; ++kt) ldsm4(BpS[kt], bBaseTS + kt * 32);
        __syncthreads();

        float acc[2][2][4];
        auto zero_acc = [&]() {
#pragma unroll
            for (int mt = 0; mt < 2; ++mt)
#pragma unroll
                for (int nt = 0; nt < 2; ++nt)
#pragma unroll
                    for (int q = 0; q < 4; ++q) acc[mt][nt][q] = 0.f;
        };
        auto gemm_step = [&](uint32_t aOff) {
            uint32_t Af[2][2][4], Bf[2][4];
            ldsm4(Af[0][0], aBaseS[0] + aOff);
            ldsm4(Af[0][1], aBaseS[1] + aOff);
            ldsm4(Bf[0], bBase2S);
#pragma unroll
            for (int kt = 0; kt < NB; ++kt) {
                int cur = kt & 1, nx = cur ^ 1;
                ldsm4(Af[nx][0], aBaseS[0] + aOff + (kt + 1) * 32);
                ldsm4(Af[nx][1], aBaseS[1] + aOff + (kt + 1) * 32);
#pragma unroll
                for (int nt = 0; nt < 2; ++nt) {
                    mma16816(acc[0][nt], Af[cur][0], BpS[kt][nt * 2], BpS[kt][nt * 2 + 1]);
                    mma16816(acc[1][nt], Af[cur][1], BpS[kt][nt * 2], BpS[kt][nt * 2 + 1]);
                }
            }
#pragma unroll
            for (int kt = NB; kt < 32; ++kt) {
                int cur = kt & 1, nx = cur ^ 1;
                if (kt < 31) {
                    ldsm4(Af[nx][0], aBaseS[0] + aOff + (kt + 1) * 32);
                    ldsm4(Af[nx][1], aBaseS[1] + aOff + (kt + 1) * 32);
                    ldsm4(Bf[nx], bBase2S + (kt - 15) * 32);
                }
#pragma unroll
                for (int nt = 0; nt < 2; ++nt) {
                    mma16816(acc[0][nt], Af[cur][0], Bf[cur][nt * 2], Bf[cur][nt * 2 + 1]);
                    mma16816(acc[1][nt], Af[cur][1], Bf[cur][nt * 2], Bf[cur][nt * 2 + 1]);
                }
            }
        };

        float4 gxn = make_float4(0.f, 0.f, 0.f, 0.f);
        if (wid == 0) gxn = g_div4[1 * B_FULL + b0 + l];

        {   // t = 0: A[b][4i+m] = s0[i]*x[b][m]
            int i  = tid & 127;
            int bh = tid >> 7;
            float s = s0s[i];
            for (int b = bh * 16; b < bh * 16 + 16; ++b) {
                float4 x = sXg[0][b];
                uint2 u;
                u.x = packbf(s * x.y, s * x.x);
                u.y = packbf(s * x.w, s * x.z);
                *reinterpret_cast<uint2*>(smem + OFF_A + ((b * PADK + 4 * i) << 1)) = u;
            }
            if (wid == 0) sXg[1][l] = gxn;
        }
        __syncthreads();
        zero_acc();
        if (wid == 0) gxn = g_div4[2 * B_FULL + b0 + l];
        gemm_step(0);

        for (int t = 1; t < T_DIV; ++t) {
            const uint32_t aOff = (uint32_t)(t & 1) * ABUF_S;
            const float4* sXc = sXg[t & 1];
#pragma unroll
            for (int mt = 0; mt < 2; ++mt) {
                int r = mt * 16 + g;
                float4 xa = sXc[r];
                float4 xb = sXc[r + 8];
                uint32_t xa01 = packbf(xa.y, xa.x), xa23 = packbf(xa.w, xa.z);
                uint32_t xb01 = packbf(xb.y, xb.x), xb23 = packbf(xb.w, xb.z);
#pragma unroll
                for (int nt = 0; nt < 2; ++nt) {
                    int i0 = wid * 16 + nt * 8 + 2 * cc;
                    uint32_t s0p = packbf(acc[mt][nt][0], acc[mt][nt][0]);
                    uint32_t s1p = packbf(acc[mt][nt][1], acc[mt][nt][1]);
                    uint32_t s2p = packbf(acc[mt][nt][2], acc[mt][nt][2]);
                    uint32_t s3p = packbf(acc[mt][nt][3], acc[mt][nt][3]);
                    uint4 ua, ub;
                    ua.x = mulbf2(s0p, xa01); ua.y = mulbf2(s0p, xa23);
                    ua.z = mulbf2(s1p, xa01); ua.w = mulbf2(s1p, xa23);
                    *reinterpret_cast<uint4*>(smem + OFF_A + aOff + ((r * PADK + 4 * i0) << 1)) = ua;
                    ub.x = mulbf2(s2p, xb01); ub.y = mulbf2(s2p, xb23);
                    ub.z = mulbf2(s3p, xb01); ub.w = mulbf2(s3p, xb23);
                    *reinterpret_cast<uint4*>(smem + OFF_A + aOff + (((r + 8) * PADK + 4 * i0) << 1)) = ub;
                }
            }
            if (wid == 0 && t + 1 < T_DIV) sXg[(t + 1) & 1][l] = gxn;

            __syncthreads();

            zero_acc();
            if (wid == 0 && t + 2 < T_DIV) gxn = g_div4[(t + 2) * B_FULL + b0 + l];
            gemm_step(aOff);
        }

#pragma unroll
        for (int mt = 0; mt < 2; ++mt) {
            int r = mt * 16 + g;
            float p0 = 0.f, p1 = 0.f;
#pragma unroll
            for (int nt = 0; nt < 2; ++nt) {
                int i0 = wid * 16 + nt * 8 + 2 * cc;
                float w0 = wls[i0], w1 = wls[i0 + 1];
                p0 += acc[mt][nt][0] * w0 + acc[mt][nt][1] * w1;
                p1 += acc[mt][nt][2] * w0 + acc[mt][nt][3] * w1;
            }
            sRed[r * 32 + wid * 4 + cc]       = p0;
            sRed[(r + 8) * 32 + wid * 4 + cc] = p1;
        }
        __syncthreads();
        if (tid < 32) {
            float sum = 0.f;
#pragma unroll
            for (int q = 0; q < 32; ++q) sum += sRed[tid * 32 + q];
            g_logits[(b0 + tid) * C_CLS + c] = sum;
        }
    }
}

// ---------------------------------------------------------------------------
// Kernel 3: log_softmax over C=10
// ---------------------------------------------------------------------------
__global__ void lsm_kernel(float* __restrict__ out) {
    int b = blockIdx.x * blockDim.x + threadIdx.x;
    if (b >= B_FULL) return;
    float v[C_CLS];
    float mx = -INFINITY;
#pragma unroll
    for (int c = 0; c < C_CLS; ++c) {
        v[c] = g_logits[b * C_CLS + c];
        mx = fmaxf(mx, v[c]);
    }
    float s = 0.f;
#pragma unroll
    for (int c = 0; c < C_CLS; ++c) s += expf(v[c] - mx);
    float lg = mx + logf(s);
#pragma unroll
    for (int c = 0; c < C_CLS; ++c) out[b * C_CLS + c] = v[c] - lg;
}

// ---------------------------------------------------------------------------
// Entry point
// ---------------------------------------------------------------------------
extern "C" void kernel_launch(void* const* d_in, const int* in_sizes, int n_in,
                              void* d_out, int out_size) {
    const float* tensor  = (const float*)d_in[0];   // (2048, 1024)
    const float* w_first = (const float*)d_in[1];   // (10, 1, 4, 128)
    const float* w_mid   = (const float*)d_in[2];   // (10, 128, 4, 128)
    const float* w_last  = (const float*)d_in[3];   // (10, 128, 4, 1)
    float* out = (float*)d_out;                     // (2048, 10)

    cudaFuncSetAttribute(rec_hmma_kernel, cudaFuncAttributeMaxDynamicSharedMemorySize, SMEM_BYTES);

    feat_kernel<<<(B_FULL * T_DIV) / 256, 256>>>(tensor);
    rec_hmma_kernel<<<N_GRID, NTHR, SMEM_BYTES>>>(w_first, w_mid, w_last);
    lsm_kernel<<<(B_FULL + 255) / 256, 256>>>(out);
}

// round 17
// speedup vs baseline: 1.4755x; 1.0180x over previous
#include <cuda_runtime.h>
#include <cuda_bf16.h>
#include <math.h>
#include <cstdint>

// ---------------------------------------------------------------------------
// Problem constants
// ---------------------------------------------------------------------------
namespace {
constexpr int B_FULL  = 2048;
constexpr int N_PIX   = 1024;
constexpr int T_DIV   = 64;
constexpr int C_CLS   = 10;
constexpr int PER_DIV = 16;
constexpr int K_DIM   = 512;          // k = i*4 + m (w_mid memory order)
constexpr int R_RANK  = 128;
constexpr int NTHR    = 256;
constexpr int NB      = 12;           // k-tiles with B permanently in registers

constexpr int PADK    = 520;          // A/temp row stride (halves); 1040 mod 128 = 16
constexpr int PADB2   = 328;          // B2 row stride (halves);  656 mod 128 = 16
constexpr int ABUF_S  = 32 * PADK * 2;             // small A buffer = 33280 B

// smem byte offsets
constexpr int OFF_B2  = 0;                           // [128][328] bf16 (k 192..511) = 83968
constexpr int OFF_A   = OFF_B2 + R_RANK * PADB2 * 2; // 133120 B (A / temp B staging)
constexpr int OFF_X   = OFF_A + R_RANK * PADK * 2;   // 4 x 64 float4 = 4096
constexpr int OFF_S0  = OFF_X + 4096;                // 128 f32
constexpr int OFF_WL  = OFF_S0 + 512;                // 128 f32
constexpr int OFF_RED = OFF_WL + 512;                // 128*16 f32 = 8192
constexpr int SMEM_BYTES = OFF_RED + 8192;           // 230400

// tasks: 148 big (BT=128, one per SM) + 48 small (BT=32, class 9 rows 512+)
constexpr int N_BIG   = 148;
constexpr int N_GRID  = 196;
}

// ---------------------------------------------------------------------------
// Device scratch
// ---------------------------------------------------------------------------
__device__ float4 g_div4[T_DIV * B_FULL];      // [t][b] -> M=4 features
__device__ float  g_logits[B_FULL * C_CLS];    // [b][c]

// ---------------------------------------------------------------------------
// asm helpers
// ---------------------------------------------------------------------------
__device__ __forceinline__ uint32_t smem_to_u32(const void* p) {
    uint32_t a;
    asm("{ .reg .u64 t; cvta.to.shared.u64 t, %1; cvt.u32.u64 %0, t; }" : "=r"(a) : "l"(p));
    return a;
}
__device__ __forceinline__ void ldsm4(uint32_t* r, uint32_t addr) {
    asm volatile("ldmatrix.sync.aligned.m8n8.x4.shared.b16 {%0,%1,%2,%3}, [%4];"
                 : "=r"(r[0]), "=r"(r[1]), "=r"(r[2]), "=r"(r[3]) : "r"(addr));
}
__device__ __forceinline__ void mma16816(float* d, const uint32_t* a, uint32_t b0, uint32_t b1) {
    asm volatile("mma.sync.aligned.m16n8k16.row.col.f32.bf16.bf16.f32 "
                 "{%0,%1,%2,%3}, {%4,%5,%6,%7}, {%8,%9}, {%0,%1,%2,%3};"
                 : "+f"(d[0]), "+f"(d[1]), "+f"(d[2]), "+f"(d[3])
                 : "r"(a[0]), "r"(a[1]), "r"(a[2]), "r"(a[3]), "r"(b0), "r"(b1));
}
__device__ __forceinline__ uint32_t packbf(float hi, float lo) {
    uint32_t u;
    asm("cvt.rn.bf16x2.f32 %0, %1, %2;" : "=r"(u) : "f"(hi), "f"(lo));
    return u;
}
__device__ __forceinline__ uint32_t mulbf2(uint32_t a, uint32_t b) {
    uint32_t d;
    asm("mul.bf16x2 %0, %1, %2;" : "=r"(d) : "r"(a), "r"(b));
    return d;
}
__device__ __forceinline__ void bar_sync128(int id) {
    asm volatile("bar.sync %0, 128;" :: "r"(id) : "memory");
}

// ---------------------------------------------------------------------------
// Kernel 1: feature map + division averaging
// ---------------------------------------------------------------------------
__global__ void feat_kernel(const float* __restrict__ tensor) {
    int idx = blockIdx.x * blockDim.x + threadIdx.x;
    if (idx >= B_FULL * T_DIV) return;
    int b = idx >> 6;
    int t = idx & (T_DIV - 1);
    const float4* p = reinterpret_cast<const float4*>(tensor + b * N_PIX + t * PER_DIV);
    float a0 = 0.f, a1 = 0.f, a2 = 0.f, a3 = 0.f;
#pragma unroll
    for (int j = 0; j < 4; ++j) {
        float4 v = p[j];
        float xs[4] = {v.x, v.y, v.z, v.w};
#pragma unroll
        for (int q = 0; q < 4; ++q) {
            float ang = 1.57079632679489662f * xs[q];
            float s, c;
            sincosf(ang, &s, &c);
            float c2 = c * c, s2 = s * s;
            a0 += c2 * c; a1 += c2 * s; a2 += c * s2; a3 += s2 * s;
        }
    }
    const float inv = 1.0f / (float)PER_DIV;
    g_div4[t * B_FULL + b] = make_float4(a0 * inv, a1 * inv, a2 * inv, a3 * inv);
}

// ---------------------------------------------------------------------------
// Kernel 2: TT recurrence, bf16 mma.sync.
// Big task (bid<148): BT=128 as TWO independent 64-row engines (half = 4
// warps, warp tile m64 x n32, own named barrier, single-buffered A rows,
// shared read-only B).  Small task: BT=32 (8 warps m32 x n16).
// B: kt 0..11 in registers (staged via temp region), kt 12..31 in sB2.
// ---------------------------------------------------------------------------
__global__ __launch_bounds__(NTHR) void rec_hmma_kernel(const float* __restrict__ w_first,
                                                        const float* __restrict__ w_mid,
                                                        const float* __restrict__ w_last) {
    extern __shared__ char smem[];
    const int tid = threadIdx.x;
    const int l   = tid & 31;
    const int wid = tid >> 5;
    const int bid = blockIdx.x;
    const bool big = (bid < N_BIG);
    const int c  = big ? (bid < 144 ? (bid >> 4) : 9) : 9;
    const int b0 = big ? (bid < 144 ? ((bid & 15) * 128) : ((bid - 144) * 128))
                       : (512 + (bid - N_BIG) * 32);

    const uint32_t smem_u = smem_to_u32(smem);
    __nv_bfloat16* sB2 = reinterpret_cast<__nv_bfloat16*>(smem + OFF_B2);
    __nv_bfloat16* sBt = reinterpret_cast<__nv_bfloat16*>(smem + OFF_A);   // temp staging
    float*  s0s  = reinterpret_cast<float*>(smem + OFF_S0);
    float*  wls  = reinterpret_cast<float*>(smem + OFF_WL);
    float4 (*sXh)[64] = reinterpret_cast<float4 (*)[64]>(smem + OFF_X);    // [half*2+buf][64]
    float*  sRed = reinterpret_cast<float*>(smem + OFF_RED);

    // ---- stage weights: k<192 -> temp A region; k>=192 -> sB2 ----
    {
        const float* Wc = w_mid + c * (K_DIM * R_RANK);
        for (int q = tid; q < K_DIM * R_RANK / 4; q += NTHR) {
            int k = q >> 5;
            int j = (q & 31) << 2;
            float4 v = *reinterpret_cast<const float4*>(Wc + k * R_RANK + j);
            if (k < 192) {
                sBt[(j + 0) * PADK + k] = __float2bfloat16(v.x);
                sBt[(j + 1) * PADK + k] = __float2bfloat16(v.y);
                sBt[(j + 2) * PADK + k] = __float2bfloat16(v.z);
                sBt[(j + 3) * PADK + k] = __float2bfloat16(v.w);
            } else {
                int kk = k - 192;
                sB2[(j + 0) * PADB2 + kk] = __float2bfloat16(v.x);
                sB2[(j + 1) * PADB2 + kk] = __float2bfloat16(v.y);
                sB2[(j + 2) * PADB2 + kk] = __float2bfloat16(v.z);
                sB2[(j + 3) * PADB2 + kk] = __float2bfloat16(v.w);
            }
        }
    }
    if (tid < R_RANK) {
        const float* wf = w_first + c * 512;
        s0s[tid] = wf[tid] + wf[128 + tid] + wf[256 + tid] + wf[384 + tid];
        const float* wl = w_last + c * 512;
        wls[tid] = wl[4 * tid] + wl[4 * tid + 1] + wl[4 * tid + 2] + wl[4 * tid + 3];
    }
    const int g  = l >> 2;
    const int cc = l & 3;

    if (big) {
        // ============ BT=128: two independent 64-row engines ================
        const int half  = wid >> 2;        // 0,1
        const int hw    = wid & 3;         // n-group within half (cols hw*32)
        const int rbase = half * 64;

        // x(0) (warps 0-3) and x(1) (warps 4-7)
        if (wid < 4) {
            int h = wid >> 1, w2 = wid & 1;
            sXh[h * 2 + 0][w2 * 32 + l] = g_div4[b0 + h * 64 + w2 * 32 + l];
        } else {
            int h = (wid - 4) >> 1, w2 = wid & 1;
            sXh[h * 2 + 1][w2 * 32 + l] = g_div4[B_FULL + b0 + h * 64 + w2 * 32 + l];
        }
        __syncthreads();

        uint32_t aBase[4], bBase2[2], bBaseT[2];
#pragma unroll
        for (int mt = 0; mt < 4; ++mt) {
            int row = rbase + mt * 16 + (l & 7) + ((l >> 3) & 1) * 8;
            aBase[mt] = smem_u + OFF_A + ((row * PADK + (l >> 4) * 8) << 1);
        }
#pragma unroll
        for (int p = 0; p < 2; ++p) {
            int row = hw * 32 + p * 16 + (l >> 4) * 8 + (l & 7);
            bBase2[p] = smem_u + OFF_B2 + ((row * PADB2 + ((l >> 3) & 1) * 8) << 1);
            bBaseT[p] = smem_u + OFF_A  + ((row * PADK  + ((l >> 3) & 1) * 8) << 1);
        }

        uint32_t Bp[NB][2][4];
#pragma unroll
        for (int kt = 0; kt < NB; ++kt) {
            ldsm4(Bp[kt][0], bBaseT[0] + kt * 32);
            ldsm4(Bp[kt][1], bBaseT[1] + kt * 32);
        }
        __syncthreads();   // Bp done before A builds overwrite temp region

        float acc[4][4][4];
        const int barid = 1 + half;

        auto zero_acc = [&]() {
#pragma unroll
            for (int mt = 0; mt < 4; ++mt)
#pragma unroll
                for (int nt = 0; nt < 4; ++nt)
#pragma unroll
                    for (int q = 0; q < 4; ++q) acc[mt][nt][q] = 0.f;
        };
        auto gemm_step = [&]() {
            uint32_t Af[2][4][4], Bf[2][2][4];
            ldsm4(Af[0][0], aBase[0]);
            ldsm4(Af[0][1], aBase[1]);
            ldsm4(Af[0][2], aBase[2]);
            ldsm4(Af[0][3], aBase[3]);
            ldsm4(Bf[0][0], bBase2[0]);        // kt=12 preload (12&1==0)
            ldsm4(Bf[0][1], bBase2[1]);
#pragma unroll
            for (int kt = 0; kt < NB; ++kt) {
                int cur = kt & 1, nx = cur ^ 1;
#pragma unroll
                for (int mt = 0; mt < 4; ++mt)
                    ldsm4(Af[nx][mt], aBase[mt] + (kt + 1) * 32);
#pragma unroll
                for (int nt = 0; nt < 4; ++nt) {
                    uint32_t b0v = Bp[kt][nt >> 1][(nt & 1) * 2];
                    uint32_t b1v = Bp[kt][nt >> 1][(nt & 1) * 2 + 1];
#pragma unroll
                    for (int mt = 0; mt < 4; ++mt)
                        mma16816(acc[mt][nt], Af[cur][mt], b0v, b1v);
                }
            }
#pragma unroll
            for (int kt = NB; kt < 32; ++kt) {
                int cur = kt & 1, nx = cur ^ 1;
                if (kt < 31) {
#pragma unroll
                    for (int mt = 0; mt < 4; ++mt)
                        ldsm4(Af[nx][mt], aBase[mt] + (kt + 1) * 32);
                    ldsm4(Bf[nx][0], bBase2[0] + (kt - 11) * 32);
                    ldsm4(Bf[nx][1], bBase2[1] + (kt - 11) * 32);
                }
#pragma unroll
                for (int nt = 0; nt < 4; ++nt) {
                    uint32_t b0v = Bf[cur][nt >> 1][(nt & 1) * 2];
                    uint32_t b1v = Bf[cur][nt >> 1][(nt & 1) * 2 + 1];
#pragma unroll
                    for (int mt = 0; mt < 4; ++mt)
                        mma16816(acc[mt][nt], Af[cur][mt], b0v, b1v);
                }
            }
        };

        // ---- t = 0: full A from s0 ----
        {
            int i  = tid & 127;
            int bh = tid >> 7;
            float s = s0s[i];
            for (int rr = 0; rr < 64; ++rr) {
                int b = bh * 64 + rr;
                float4 x = sXh[bh * 2][rr];
                uint2 u;
                u.x = packbf(s * x.y, s * x.x);
                u.y = packbf(s * x.w, s * x.z);
                *reinterpret_cast<uint2*>(smem + OFF_A + ((b * PADK + 4 * i) << 1)) = u;
            }
        }
        __syncthreads();
        zero_acc();
        float4 gxn = make_float4(0.f, 0.f, 0.f, 0.f);
        if (hw < 2) gxn = g_div4[2 * B_FULL + b0 + rbase + hw * 32 + l];   // x(2)
        gemm_step();

        // ---- steps 1..63: per-half 2-barrier skeleton ----
        for (int t = 1; t < T_DIV; ++t) {
            bar_sync128(barid);    // half: GEMM(t-1) done reading A rows

            const float4* sXc = sXh[half * 2 + (t & 1)];
#pragma unroll
            for (int mt = 0; mt < 4; ++mt) {
                int lr = mt * 16 + g;
                int r  = rbase + lr;
                float4 xa = sXc[lr];
                float4 xb = sXc[lr + 8];
                uint32_t xa01 = packbf(xa.y, xa.x), xa23 = packbf(xa.w, xa.z);
                uint32_t xb01 = packbf(xb.y, xb.x), xb23 = packbf(xb.w, xb.z);
#pragma unroll
                for (int nt = 0; nt < 4; ++nt) {
                    int i0 = hw * 32 + nt * 8 + 2 * cc;
                    uint32_t s0p = packbf(acc[mt][nt][0], acc[mt][nt][0]);
                    uint32_t s1p = packbf(acc[mt][nt][1], acc[mt][nt][1]);
                    uint32_t s2p = packbf(acc[mt][nt][2], acc[mt][nt][2]);
                    uint32_t s3p = packbf(acc[mt][nt][3], acc[mt][nt][3]);
                    uint4 ua, ub;
                    ua.x = mulbf2(s0p, xa01); ua.y = mulbf2(s0p, xa23);
                    ua.z = mulbf2(s1p, xa01); ua.w = mulbf2(s1p, xa23);
                    *reinterpret_cast<uint4*>(smem + OFF_A + ((r * PADK + 4 * i0) << 1)) = ua;
                    ub.x = mulbf2(s2p, xb01); ub.y = mulbf2(s2p, xb23);
                    ub.z = mulbf2(s3p, xb01); ub.w = mulbf2(s3p, xb23);
                    *reinterpret_cast<uint4*>(smem + OFF_A + (((r + 8) * PADK + 4 * i0) << 1)) = ub;
                }
            }
            if (hw < 2 && t + 1 < T_DIV)
                sXh[half * 2 + ((t + 1) & 1)][hw * 32 + l] = gxn;

            bar_sync128(barid);    // half: A rows rebuilt (+ x(t+1) visible)

            zero_acc();
            if (hw < 2 && t + 2 < T_DIV)
                gxn = g_div4[(t + 2) * B_FULL + b0 + rbase + hw * 32 + l];
            gemm_step();
        }

        // ---- final projection ----
#pragma unroll
        for (int mt = 0; mt < 4; ++mt) {
            int r = rbase + mt * 16 + g;
            float p0 = 0.f, p1 = 0.f;
#pragma unroll
            for (int nt = 0; nt < 4; ++nt) {
                int i0 = hw * 32 + nt * 8 + 2 * cc;
                float w0 = wls[i0], w1 = wls[i0 + 1];
                p0 += acc[mt][nt][0] * w0 + acc[mt][nt][1] * w1;
                p1 += acc[mt][nt][2] * w0 + acc[mt][nt][3] * w1;
            }
            sRed[r * 16 + hw * 4 + cc]       = p0;
            sRed[(r + 8) * 16 + hw * 4 + cc] = p1;
        }
        __syncthreads();
        if (tid < 128) {
            float sum = 0.f;
#pragma unroll
            for (int q = 0; q < 16; ++q) sum += sRed[tid * 16 + q];
            g_logits[(b0 + tid) * C_CLS + c] = sum;
        }
    } else {
        // =================== BT = 32 path (8 warps, m32 x n16) ===============
        if (wid == 0) sXh[0][l] = g_div4[b0 + l];
        __syncthreads();

        uint32_t aBaseS[2], bBase2S, bBaseTS;
#pragma unroll
        for (int mt = 0; mt < 2; ++mt)
            aBaseS[mt] = smem_u + OFF_A +
                (((mt * 16 + (l & 7) + ((l >> 3) & 1) * 8) * PADK + (l >> 4) * 8) << 1);
        {
            int row = wid * 16 + (l >> 4) * 8 + (l & 7);
            bBase2S = smem_u + OFF_B2 + ((row * PADB2 + ((l >> 3) & 1) * 8) << 1);
            bBaseTS = smem_u + OFF_A  + ((row * PADK  + ((l >> 3) & 1) * 8) << 1);
        }

        uint32_t BpS[NB][4];
#pragma unroll
        for (int kt = 0; kt < NB; ++kt) ldsm4(BpS[kt], bBaseTS + kt * 32);
        __syncthreads();

        float acc[2][2][4];
        auto zero_acc = [&]() {
#pragma unroll
            for (int mt = 0; mt < 2; ++mt)
#pragma unroll
                for (int nt = 0; nt < 2; ++nt)
#pragma unroll
                    for (int q = 0; q < 4; ++q) acc[mt][nt][q] = 0.f;
        };
        auto gemm_step = [&](uint32_t aOff) {
            uint32_t Af[2][2][4], Bf[2][4];
            ldsm4(Af[0][0], aBaseS[0] + aOff);
            ldsm4(Af[0][1], aBaseS[1] + aOff);
            ldsm4(Bf[0], bBase2S);
#pragma unroll
            for (int kt = 0; kt < NB; ++kt) {
                int cur = kt & 1, nx = cur ^ 1;
                ldsm4(Af[nx][0], aBaseS[0] + aOff + (kt + 1) * 32);
                ldsm4(Af[nx][1], aBaseS[1] + aOff + (kt + 1) * 32);
#pragma unroll
                for (int nt = 0; nt < 2; ++nt) {
                    mma16816(acc[0][nt], Af[cur][0], BpS[kt][nt * 2], BpS[kt][nt * 2 + 1]);
                    mma16816(acc[1][nt], Af[cur][1], BpS[kt][nt * 2], BpS[kt][nt * 2 + 1]);
                }
            }
#pragma unroll
            for (int kt = NB; kt < 32; ++kt) {
                int cur = kt & 1, nx = cur ^ 1;
                if (kt < 31) {
                    ldsm4(Af[nx][0], aBaseS[0] + aOff + (kt + 1) * 32);
                    ldsm4(Af[nx][1], aBaseS[1] + aOff + (kt + 1) * 32);
                    ldsm4(Bf[nx], bBase2S + (kt - 11) * 32);
                }
#pragma unroll
                for (int nt = 0; nt < 2; ++nt) {
                    mma16816(acc[0][nt], Af[cur][0], Bf[cur][nt * 2], Bf[cur][nt * 2 + 1]);
                    mma16816(acc[1][nt], Af[cur][1], Bf[cur][nt * 2], Bf[cur][nt * 2 + 1]);
                }
            }
        };

        float4 gxn = make_float4(0.f, 0.f, 0.f, 0.f);
        if (wid == 0) gxn = g_div4[1 * B_FULL + b0 + l];

        {   // t = 0
            int i  = tid & 127;
            int bh = tid >> 7;
            float s = s0s[i];
            for (int b = bh * 16; b < bh * 16 + 16; ++b) {
                float4 x = sXh[0][b];
                uint2 u;
                u.x = packbf(s * x.y, s * x.x);
                u.y = packbf(s * x.w, s * x.z);
                *reinterpret_cast<uint2*>(smem + OFF_A + ((b * PADK + 4 * i) << 1)) = u;
            }
            if (wid == 0) sXh[1][l] = gxn;
        }
        __syncthreads();
        zero_acc();
        if (wid == 0) gxn = g_div4[2 * B_FULL + b0 + l];
        gemm_step(0);

        for (int t = 1; t < T_DIV; ++t) {
            const uint32_t aOff = (uint32_t)(t & 1) * ABUF_S;
            const float4* sXc = sXh[t & 1];
#pragma unroll
            for (int mt = 0; mt < 2; ++mt) {
                int r = mt * 16 + g;
                float4 xa = sXc[r];
                float4 xb = sXc[r + 8];
                uint32_t xa01 = packbf(xa.y, xa.x), xa23 = packbf(xa.w, xa.z);
                uint32_t xb01 = packbf(xb.y, xb.x), xb23 = packbf(xb.w, xb.z);
#pragma unroll
                for (int nt = 0; nt < 2; ++nt) {
                    int i0 = wid * 16 + nt * 8 + 2 * cc;
                    uint32_t s0p = packbf(acc[mt][nt][0], acc[mt][nt][0]);
                    uint32_t s1p = packbf(acc[mt][nt][1], acc[mt][nt][1]);
                    uint32_t s2p = packbf(acc[mt][nt][2], acc[mt][nt][2]);
                    uint32_t s3p = packbf(acc[mt][nt][3], acc[mt][nt][3]);
                    uint4 ua, ub;
                    ua.x = mulbf2(s0p, xa01); ua.y = mulbf2(s0p, xa23);
                    ua.z = mulbf2(s1p, xa01); ua.w = mulbf2(s1p, xa23);
                    *reinterpret_cast<uint4*>(smem + OFF_A + aOff + ((r * PADK + 4 * i0) << 1)) = ua;
                    ub.x = mulbf2(s2p, xb01); ub.y = mulbf2(s2p, xb23);
                    ub.z = mulbf2(s3p, xb01); ub.w = mulbf2(s3p, xb23);
                    *reinterpret_cast<uint4*>(smem + OFF_A + aOff + (((r + 8) * PADK + 4 * i0) << 1)) = ub;
                }
            }
            if (wid == 0 && t + 1 < T_DIV) sXh[(t + 1) & 1][l] = gxn;

            __syncthreads();

            zero_acc();
            if (wid == 0 && t + 2 < T_DIV) gxn = g_div4[(t + 2) * B_FULL + b0 + l];
            gemm_step(aOff);
        }

#pragma unroll
        for (int mt = 0; mt < 2; ++mt) {
            int r = mt * 16 + g;
            float p0 = 0.f, p1 = 0.f;
#pragma unroll
            for (int nt = 0; nt < 2; ++nt) {
                int i0 = wid * 16 + nt * 8 + 2 * cc;
                float w0 = wls[i0], w1 = wls[i0 + 1];
                p0 += acc[mt][nt][0] * w0 + acc[mt][nt][1] * w1;
                p1 += acc[mt][nt][2] * w0 + acc[mt][nt][3] * w1;
            }
            sRed[r * 32 + wid * 4 + cc]       = p0;
            sRed[(r + 8) * 32 + wid * 4 + cc] = p1;
        }
        __syncthreads();
        if (tid < 32) {
            float sum = 0.f;
#pragma unroll
            for (int q = 0; q < 32; ++q) sum += sRed[tid * 32 + q];
            g_logits[(b0 + tid) * C_CLS + c] = sum;
        }
    }
}

// ---------------------------------------------------------------------------
// Kernel 3: log_softmax over C=10
// ---------------------------------------------------------------------------
__global__ void lsm_kernel(float* __restrict__ out) {
    int b = blockIdx.x * blockDim.x + threadIdx.x;
    if (b >= B_FULL) return;
    float v[C_CLS];
    float mx = -INFINITY;
#pragma unroll
    for (int c = 0; c < C_CLS; ++c) {
        v[c] = g_logits[b * C_CLS + c];
        mx = fmaxf(mx, v[c]);
    }
    float s = 0.f;
#pragma unroll
    for (int c = 0; c < C_CLS; ++c) s += expf(v[c] - mx);
    float lg = mx + logf(s);
#pragma unroll
    for (int c = 0; c < C_CLS; ++c) out[b * C_CLS + c] = v[c] - lg;
}

// ---------------------------------------------------------------------------
// Entry point
// ---------------------------------------------------------------------------
extern "C" void kernel_launch(void* const* d_in, const int* in_sizes, int n_in,
                              void* d_out, int out_size) {
    const float* tensor  = (const float*)d_in[0];   // (2048, 1024)
    const float* w_first = (const float*)d_in[1];   // (10, 1, 4, 128)
    const float* w_mid   = (const float*)d_in[2];   // (10, 128, 4, 128)
    const float* w_last  = (const float*)d_in[3];   // (10, 128, 4, 1)
    float* out = (float*)d_out;                     // (2048, 10)

    cudaFuncSetAttribute(rec_hmma_kernel, cudaFuncAttributeMaxDynamicSharedMemorySize, SMEM_BYTES);

    feat_kernel<<<(B_FULL * T_DIV) / 256, 256>>>(tensor);
    rec_hmma_kernel<<<N_GRID, NTHR, SMEM_BYTES>>>(w_first, w_mid, w_last);
    lsm_kernel<<<(B_FULL + 255) / 256, 256>>>(out);
}